// round 1
// baseline (speedup 1.0000x reference)
#include <cuda_runtime.h>
#include <cmath>

// Problem constants
constexpr int Bn = 2;
constexpr int Tn = 2048;
constexpr int Cn = 1024;
constexpr int Hn = 16;
constexpr int HDn = 64;
constexpr int Mn = Bn * Tn;   // 4096
constexpr int WS = 64;
constexpr int HW = WS / 2;    // 32

// Scratch (device globals -- no allocation allowed)
__device__ float g_q[Mn * Cn];
__device__ float g_k[Mn * Cn];
__device__ float g_v[Mn * Cn];
__device__ float g_o[Mn * Cn];

// ---------------------------------------------------------------------------
// SGEMM:  C[m][n] = sum_k A[m][k] * W[n][k] + bias[n]   (torch Linear, NT)
// A: [M,K] row-major, W: [N,K] row-major. M%128==0, N%128==0, K%16==0 assumed.
// 128x128 tile, BK=16, 256 threads, 8x8 accum per thread.
// ---------------------------------------------------------------------------
constexpr int BM = 128, BN = 128, BK = 16;

__global__ __launch_bounds__(256) void sgemm_nt_bias(
    const float* __restrict__ A, const float* __restrict__ W,
    const float* __restrict__ bias, float* __restrict__ C_,
    int M, int N, int K)
{
    __shared__ float As[BK][BM];
    __shared__ float Bs[BK][BN];

    const int tid = threadIdx.x;
    const int m0 = blockIdx.y * BM;
    const int n0 = blockIdx.x * BN;

    // loader mapping: 512 float4 per tile; thread handles id=tid and id=tid+256
    const int ar = tid >> 2;            // 0..63
    const int ac = (tid & 3) * 4;       // 0,4,8,12

    const int tr = tid >> 4;            // 0..15
    const int tc = tid & 15;            // 0..15

    float acc[8][8];
#pragma unroll
    for (int i = 0; i < 8; i++)
#pragma unroll
        for (int j = 0; j < 8; j++) acc[i][j] = 0.0f;

    for (int k0 = 0; k0 < K; k0 += BK) {
        float4 a0 = *(const float4*)&A[(m0 + ar)      * K + k0 + ac];
        float4 a1 = *(const float4*)&A[(m0 + ar + 64) * K + k0 + ac];
        float4 b0 = *(const float4*)&W[(n0 + ar)      * K + k0 + ac];
        float4 b1 = *(const float4*)&W[(n0 + ar + 64) * K + k0 + ac];

        As[ac + 0][ar] = a0.x; As[ac + 1][ar] = a0.y;
        As[ac + 2][ar] = a0.z; As[ac + 3][ar] = a0.w;
        As[ac + 0][ar + 64] = a1.x; As[ac + 1][ar + 64] = a1.y;
        As[ac + 2][ar + 64] = a1.z; As[ac + 3][ar + 64] = a1.w;

        Bs[ac + 0][ar] = b0.x; Bs[ac + 1][ar] = b0.y;
        Bs[ac + 2][ar] = b0.z; Bs[ac + 3][ar] = b0.w;
        Bs[ac + 0][ar + 64] = b1.x; Bs[ac + 1][ar + 64] = b1.y;
        Bs[ac + 2][ar + 64] = b1.z; Bs[ac + 3][ar + 64] = b1.w;

        __syncthreads();

#pragma unroll
        for (int kk = 0; kk < BK; kk++) {
            float a[8], b[8];
            *(float4*)&a[0] = *(const float4*)&As[kk][tr * 4];
            *(float4*)&a[4] = *(const float4*)&As[kk][tr * 4 + 64];
            *(float4*)&b[0] = *(const float4*)&Bs[kk][tc * 4];
            *(float4*)&b[4] = *(const float4*)&Bs[kk][tc * 4 + 64];
#pragma unroll
            for (int i = 0; i < 8; i++)
#pragma unroll
                for (int j = 0; j < 8; j++)
                    acc[i][j] += a[i] * b[j];
        }
        __syncthreads();
    }

    // epilogue: rows {rg*64 + tr*4 + i}, cols {cg*64 + tc*4 + j}
#pragma unroll
    for (int rg = 0; rg < 2; rg++) {
#pragma unroll
        for (int i = 0; i < 4; i++) {
            int row = m0 + rg * 64 + tr * 4 + i;
#pragma unroll
            for (int cg = 0; cg < 2; cg++) {
                int col = n0 + cg * 64 + tc * 4;
                float4 v;
                v.x = acc[rg * 4 + i][cg * 4 + 0] + bias[col + 0];
                v.y = acc[rg * 4 + i][cg * 4 + 1] + bias[col + 1];
                v.z = acc[rg * 4 + i][cg * 4 + 2] + bias[col + 2];
                v.w = acc[rg * 4 + i][cg * 4 + 3] + bias[col + 3];
                *(float4*)&C_[(size_t)row * N + col] = v;
            }
        }
    }
}

// ---------------------------------------------------------------------------
// Sliding-window attention. Q/K/V in [B,T,C] row-major (C = H*HD, head h at
// column h*64). Row i attends to keys j in [i-32, i+32).
// Block: 16 queries of one (b,h); 256 threads = 8 warps; warp handles
// queries {w, w+8}. Key span for block: [q0-32, q0+15+31] -> 79 rows (pad 80).
// ---------------------------------------------------------------------------
constexpr int QB = 16;
constexpr int KROWS = 80;

__global__ __launch_bounds__(256) void attn_win(
    const float* __restrict__ Qm, const float* __restrict__ Km,
    const float* __restrict__ Vm, float* __restrict__ Om)
{
    __shared__ float Ks[KROWS][65];   // +1 pad: scores read stride-65 -> no conflicts
    __shared__ float Vs[KROWS][64];
    __shared__ float Qs[QB][64];
    __shared__ float Ps[8][64];

    const int tid = threadIdx.x;
    const int bh = blockIdx.y;
    const int b = bh >> 4;
    const int h = bh & 15;
    const int q0 = blockIdx.x * QB;
    const int kbase = q0 - HW;

    // load Q tile: 16x64 = 256 float4
    {
        int r = tid >> 4;
        int c = (tid & 15) * 4;
        *(float4*)&Qs[r][c] =
            *(const float4*)&Qm[((size_t)(b * Tn + q0 + r)) * Cn + h * 64 + c];
    }
    // load K,V tiles: 80 rows x 16 float4
    for (int id = tid; id < KROWS * 16; id += 256) {
        int r = id >> 4;
        int c = (id & 15) * 4;
        int j = kbase + r;
        float4 kv, vv;
        if (j >= 0 && j < Tn) {
            size_t base = ((size_t)(b * Tn + j)) * Cn + h * 64 + c;
            kv = *(const float4*)&Km[base];
            vv = *(const float4*)&Vm[base];
        } else {
            kv = make_float4(0.f, 0.f, 0.f, 0.f);
            vv = kv;
        }
        Ks[r][c + 0] = kv.x; Ks[r][c + 1] = kv.y;
        Ks[r][c + 2] = kv.z; Ks[r][c + 3] = kv.w;
        *(float4*)&Vs[r][c] = vv;
    }
    __syncthreads();

    const int w = tid >> 5;
    const int l = tid & 31;
    const float scale = 0.125f;   // 64^-0.5

    for (int qi = w; qi < QB; qi += 8) {
        const int q = q0 + qi;
        // lane handles window offsets t = l and t = l+32; smem row = qi + t
        const int kr0 = qi + l;
        const int kr1 = qi + l + 32;
        float s0 = 0.f, s1 = 0.f;
#pragma unroll 16
        for (int d = 0; d < 64; d++) {
            float qd = Qs[qi][d];
            s0 += qd * Ks[kr0][d];
            s1 += qd * Ks[kr1][d];
        }
        s0 *= scale; s1 *= scale;
        const int j0 = q - HW + l;
        const int j1 = j0 + 32;
        if (j0 < 0 || j0 >= Tn) s0 = -INFINITY;
        if (j1 >= Tn)           s1 = -INFINITY;   // j1 >= 0 always (q - 32 + 32 >= 0)

        float m = fmaxf(s0, s1);
#pragma unroll
        for (int off = 16; off; off >>= 1)
            m = fmaxf(m, __shfl_xor_sync(0xffffffffu, m, off));
        float p0 = __expf(s0 - m);
        float p1 = __expf(s1 - m);
        float sum = p0 + p1;
#pragma unroll
        for (int off = 16; off; off >>= 1)
            sum += __shfl_xor_sync(0xffffffffu, sum, off);

        Ps[w][l] = p0;
        Ps[w][l + 32] = p1;
        __syncwarp();

        const float inv = 1.0f / sum;
        float acc0 = 0.f, acc1 = 0.f;
#pragma unroll 8
        for (int t = 0; t < 64; t++) {
            float pr = Ps[w][t];
            acc0 += pr * Vs[qi + t][l];
            acc1 += pr * Vs[qi + t][l + 32];
        }
        size_t ob = ((size_t)(b * Tn + q)) * Cn + h * 64;
        Om[ob + l]      = acc0 * inv;
        Om[ob + l + 32] = acc1 * inv;
        __syncwarp();   // Ps[w] reused next qi iteration
    }
}

// ---------------------------------------------------------------------------
extern "C" void kernel_launch(void* const* d_in, const int* in_sizes, int n_in,
                              void* d_out, int out_size)
{
    const float* x   = (const float*)d_in[0];
    const float* q_w = (const float*)d_in[1];
    const float* q_b = (const float*)d_in[2];
    const float* k_w = (const float*)d_in[3];
    const float* k_b = (const float*)d_in[4];
    const float* v_w = (const float*)d_in[5];
    const float* v_b = (const float*)d_in[6];
    const float* o_w = (const float*)d_in[7];
    const float* o_b = (const float*)d_in[8];
    float* out = (float*)d_out;

    float *gq, *gk, *gv, *go;
    cudaGetSymbolAddress((void**)&gq, g_q);
    cudaGetSymbolAddress((void**)&gk, g_k);
    cudaGetSymbolAddress((void**)&gv, g_v);
    cudaGetSymbolAddress((void**)&go, g_o);

    dim3 gemm_grid(Cn / BN, Mn / BM);   // (8, 32)
    sgemm_nt_bias<<<gemm_grid, 256>>>(x,  q_w, q_b, gq, Mn, Cn, Cn);
    sgemm_nt_bias<<<gemm_grid, 256>>>(x,  k_w, k_b, gk, Mn, Cn, Cn);
    sgemm_nt_bias<<<gemm_grid, 256>>>(x,  v_w, v_b, gv, Mn, Cn, Cn);

    dim3 attn_grid(Tn / QB, Bn * Hn);   // (128, 32)
    attn_win<<<attn_grid, 256>>>(gq, gk, gv, go);

    sgemm_nt_bias<<<gemm_grid, 256>>>(go, o_w, o_b, out, Mn, Cn, Cn);
}

// round 3
// speedup vs baseline: 2.4560x; 2.4560x over previous
#include <cuda_runtime.h>
#include <cuda_bf16.h>
#include <cmath>
#include <cstdint>

// Problem constants
constexpr int Bn = 2;
constexpr int Tn = 2048;
constexpr int Cn = 1024;
constexpr int Mn = Bn * Tn;   // 4096
constexpr int HW = 32;        // window half

// ---------------------------------------------------------------------------
// Scratch (device globals -- no allocation allowed)
// ---------------------------------------------------------------------------
__device__ __align__(256) float g_q[Mn * Cn];
__device__ __align__(256) float g_k[Mn * Cn];
__device__ __align__(256) float g_v[Mn * Cn];
__device__ __align__(256) __nv_bfloat16 g_xh[Mn * Cn];
__device__ __align__(256) __nv_bfloat16 g_xl[Mn * Cn];
__device__ __align__(256) __nv_bfloat16 g_wh[3 * Cn * Cn];
__device__ __align__(256) __nv_bfloat16 g_wl[3 * Cn * Cn];
__device__ __align__(256) __nv_bfloat16 g_ah[Mn * Cn];
__device__ __align__(256) __nv_bfloat16 g_al[Mn * Cn];

// ---------------------------------------------------------------------------
// PTX helpers (base-ISA only: cp.async / ldmatrix / mma.sync)
// ---------------------------------------------------------------------------
__device__ __forceinline__ uint32_t smem_u32(const void* p) {
    uint32_t a;
    asm("{ .reg .u64 t; cvta.to.shared.u64 t, %1; cvt.u32.u64 %0, t; }"
        : "=r"(a) : "l"(p));
    return a;
}

__device__ __forceinline__ void cp16(uint32_t s, const void* g) {
    asm volatile("cp.async.cg.shared.global [%0], [%1], 16;" :: "r"(s), "l"(g));
}

__device__ __forceinline__ void ldm_x4(uint32_t& r0, uint32_t& r1,
                                       uint32_t& r2, uint32_t& r3, uint32_t a) {
    asm volatile("ldmatrix.sync.aligned.m8n8.x4.shared.b16 {%0,%1,%2,%3}, [%4];"
                 : "=r"(r0), "=r"(r1), "=r"(r2), "=r"(r3) : "r"(a));
}

__device__ __forceinline__ void mma_bf16(float* c, const uint32_t* a,
                                         const uint32_t* b) {
    asm volatile(
        "mma.sync.aligned.m16n8k16.row.col.f32.bf16.bf16.f32 "
        "{%0,%1,%2,%3}, {%4,%5,%6,%7}, {%8,%9}, {%0,%1,%2,%3};"
        : "+f"(c[0]), "+f"(c[1]), "+f"(c[2]), "+f"(c[3])
        : "r"(a[0]), "r"(a[1]), "r"(a[2]), "r"(a[3]), "r"(b[0]), "r"(b[1]));
}

// ---------------------------------------------------------------------------
// bf16x3 mma.sync GEMM:  out[m][n] = sum_k A[m][k]*W[n][k] + bias[n]
// A ~ (ah + al), W ~ (wh + wl); passes: hh + hl + lh.
// 128x128 tile, BK=32, 256 threads (8 warps, 2x4), warp tile 64x32.
// smem tile [128][32] bf16, 64B rows, chunk swizzle c ^ ((row>>1)&3).
// 2-stage cp.async double buffer. blockIdx.z selects QKV slice.
// ---------------------------------------------------------------------------
constexpr int GBK = 32;
constexpr int KITERS = Cn / GBK;            // 32
constexpr int TIL = 128 * GBK * 2;          // 8192 bytes per matrix tile
constexpr int STAGE = 4 * TIL;              // Ah,Al,Bh,Bl = 32 KB
constexpr int SM_TOTAL = 2 * STAGE;         // 64 KB

__global__ void __launch_bounds__(256) gemm_bf16x3(
    const __nv_bfloat16* __restrict__ ah, const __nv_bfloat16* __restrict__ al,
    const __nv_bfloat16* __restrict__ wh, const __nv_bfloat16* __restrict__ wl,
    const float* __restrict__ b0, const float* __restrict__ b1, const float* __restrict__ b2,
    float* __restrict__ o0, float* __restrict__ o1, float* __restrict__ o2)
{
    extern __shared__ char smem[];
    const uint32_t sb = smem_u32(smem);
    const int tid = threadIdx.x;
    const int z = blockIdx.z;
    const int m0 = blockIdx.y * 128;
    const int n0 = blockIdx.x * 128;

    const __nv_bfloat16* Bh = wh + (size_t)z * Cn * Cn;
    const __nv_bfloat16* Bl = wl + (size_t)z * Cn * Cn;
    const float* bias = (z == 0) ? b0 : (z == 1) ? b1 : b2;
    float* out = (z == 0) ? o0 : (z == 1) ? o1 : o2;

    const int lane = tid & 31;
    const int wid = tid >> 5;
    const int wm = wid >> 2;       // 0..1  (64 rows each)
    const int wn = wid & 3;        // 0..3  (32 cols each)

    // ---- loader indices (per-thread, fixed): 2 rows per matrix per stage ----
    const int lrow0 = tid >> 2;            // 0..63
    const int lrow1 = lrow0 + 64;          // 64..127
    const int lc = tid & 3;                // 16B chunk 0..3
    const uint32_t soff0 = (uint32_t)(lrow0 * 64 + ((lc ^ ((lrow0 >> 1) & 3)) << 4));
    const uint32_t soff1 = (uint32_t)(lrow1 * 64 + ((lc ^ ((lrow1 >> 1) & 3)) << 4));

    auto load_stage = [&](int it, int s) {
        const int k0 = it * GBK;
        const uint32_t st = sb + s * STAGE;
        size_t ga0 = (size_t)(m0 + lrow0) * Cn + k0 + lc * 8;
        size_t ga1 = (size_t)(m0 + lrow1) * Cn + k0 + lc * 8;
        size_t gb0 = (size_t)(n0 + lrow0) * Cn + k0 + lc * 8;
        size_t gb1 = (size_t)(n0 + lrow1) * Cn + k0 + lc * 8;
        cp16(st + soff0,            ah + ga0);
        cp16(st + soff1,            ah + ga1);
        cp16(st + TIL + soff0,      al + ga0);
        cp16(st + TIL + soff1,      al + ga1);
        cp16(st + 2 * TIL + soff0,  Bh + gb0);
        cp16(st + 2 * TIL + soff1,  Bh + gb1);
        cp16(st + 3 * TIL + soff0,  Bl + gb0);
        cp16(st + 3 * TIL + soff1,  Bl + gb1);
        asm volatile("cp.async.commit_group;" ::: "memory");
    };

    // ---- frag load addresses (per-thread, depend only on ks) ----
    // A: row = wm*64 + mi*16 + (lane&15), kchunk = ks*2 + (lane>>4)
    const int arow = wm * 64 + (lane & 15);
    // B: nrow = wn*32 + p*16 + (lane&7) + ((lane>>4)<<3), kchunk = ks*2 + ((lane>>3)&1)
    const int brow = wn * 32 + (lane & 7) + ((lane >> 4) << 3);

    float acc[4][4][4];
#pragma unroll
    for (int i = 0; i < 4; i++)
#pragma unroll
        for (int j = 0; j < 4; j++)
#pragma unroll
            for (int r = 0; r < 4; r++) acc[i][j][r] = 0.0f;

    load_stage(0, 0);

    for (int it = 0; it < KITERS; it++) {
        if (it + 1 < KITERS) {
            load_stage(it + 1, (it + 1) & 1);
            asm volatile("cp.async.wait_group 1;" ::: "memory");
        } else {
            asm volatile("cp.async.wait_group 0;" ::: "memory");
        }
        __syncthreads();

        const uint32_t st = sb + (it & 1) * STAGE;
#pragma unroll
        for (int ks = 0; ks < 2; ks++) {
            uint32_t fah[4][4], fal[4][4], fbh[4][2], fbl[4][2];
            // A frags: 4 m-tiles, hi and lo
            const int akc = ks * 2 + (lane >> 4);
#pragma unroll
            for (int mi = 0; mi < 4; mi++) {
                int row = arow + mi * 16;
                uint32_t off = (uint32_t)(row * 64 + (((akc) ^ ((row >> 1) & 3)) << 4));
                ldm_x4(fah[mi][0], fah[mi][1], fah[mi][2], fah[mi][3], st + off);
                ldm_x4(fal[mi][0], fal[mi][1], fal[mi][2], fal[mi][3], st + TIL + off);
            }
            // B frags: 2 ldmatrix.x4 cover 4 n-tiles, hi and lo
            const int bkc = ks * 2 + ((lane >> 3) & 1);
#pragma unroll
            for (int p = 0; p < 2; p++) {
                int row = brow + p * 16;
                uint32_t off = (uint32_t)(row * 64 + (((bkc) ^ ((row >> 1) & 3)) << 4));
                ldm_x4(fbh[2 * p][0], fbh[2 * p][1], fbh[2 * p + 1][0], fbh[2 * p + 1][1],
                       st + 2 * TIL + off);
                ldm_x4(fbl[2 * p][0], fbl[2 * p][1], fbl[2 * p + 1][0], fbl[2 * p + 1][1],
                       st + 3 * TIL + off);
            }
#pragma unroll
            for (int mi = 0; mi < 4; mi++)
#pragma unroll
                for (int ni = 0; ni < 4; ni++) {
                    mma_bf16(acc[mi][ni], fah[mi], fbh[ni]);
                    mma_bf16(acc[mi][ni], fah[mi], fbl[ni]);
                    mma_bf16(acc[mi][ni], fal[mi], fbh[ni]);
                }
        }
        __syncthreads();
    }

    // ---- epilogue: acc -> global with bias ----
#pragma unroll
    for (int mi = 0; mi < 4; mi++) {
#pragma unroll
        for (int h = 0; h < 2; h++) {
            int row = m0 + wm * 64 + mi * 16 + (lane >> 2) + h * 8;
            float* op = out + (size_t)row * Cn;
#pragma unroll
            for (int ni = 0; ni < 4; ni++) {
                int col = n0 + wn * 32 + ni * 8 + (lane & 3) * 2;
                float2 o;
                o.x = acc[mi][ni][h * 2 + 0] + bias[col];
                o.y = acc[mi][ni][h * 2 + 1] + bias[col + 1];
                *(float2*)&op[col] = o;
            }
        }
    }
}

// ---------------------------------------------------------------------------
// fp32 -> bf16 hi/lo split
// ---------------------------------------------------------------------------
__global__ void __launch_bounds__(256) convert_hilo(
    const float* __restrict__ in, __nv_bfloat16* __restrict__ hi,
    __nv_bfloat16* __restrict__ lo, int n)
{
    int i = (blockIdx.x * 256 + threadIdx.x) * 4;
    if (i >= n) return;
    float4 v = *(const float4*)&in[i];
    __nv_bfloat16 h0 = __float2bfloat16_rn(v.x);
    __nv_bfloat16 h1 = __float2bfloat16_rn(v.y);
    __nv_bfloat16 h2 = __float2bfloat16_rn(v.z);
    __nv_bfloat16 h3 = __float2bfloat16_rn(v.w);
    __nv_bfloat162 hp0; hp0.x = h0; hp0.y = h1;
    __nv_bfloat162 hp1; hp1.x = h2; hp1.y = h3;
    *(__nv_bfloat162*)&hi[i] = hp0;
    *(__nv_bfloat162*)&hi[i + 2] = hp1;
    __nv_bfloat162 lp0, lp1;
    lp0.x = __float2bfloat16_rn(v.x - __bfloat162float(h0));
    lp0.y = __float2bfloat16_rn(v.y - __bfloat162float(h1));
    lp1.x = __float2bfloat16_rn(v.z - __bfloat162float(h2));
    lp1.y = __float2bfloat16_rn(v.w - __bfloat162float(h3));
    *(__nv_bfloat162*)&lo[i] = lp0;
    *(__nv_bfloat162*)&lo[i + 2] = lp1;
}

// ---------------------------------------------------------------------------
// Sliding-window attention (fp32), emits hi/lo bf16 for the O projection.
// ---------------------------------------------------------------------------
constexpr int QB = 16;
constexpr int KROWS = 80;

__global__ void __launch_bounds__(256) attn_win(
    const float* __restrict__ Qm, const float* __restrict__ Km,
    const float* __restrict__ Vm,
    __nv_bfloat16* __restrict__ Oh, __nv_bfloat16* __restrict__ Ol)
{
    __shared__ float Ks[KROWS][65];
    __shared__ float Vs[KROWS][64];
    __shared__ float Qs[QB][64];
    __shared__ float Ps[8][64];

    const int tid = threadIdx.x;
    const int bh = blockIdx.y;
    const int b = bh >> 4;
    const int h = bh & 15;
    const int q0 = blockIdx.x * QB;
    const int kbase = q0 - HW;

    {
        int r = tid >> 4;
        int c = (tid & 15) * 4;
        *(float4*)&Qs[r][c] =
            *(const float4*)&Qm[((size_t)(b * Tn + q0 + r)) * Cn + h * 64 + c];
    }
    for (int id = tid; id < KROWS * 16; id += 256) {
        int r = id >> 4;
        int c = (id & 15) * 4;
        int j = kbase + r;
        float4 kv, vv;
        if (j >= 0 && j < Tn) {
            size_t base = ((size_t)(b * Tn + j)) * Cn + h * 64 + c;
            kv = *(const float4*)&Km[base];
            vv = *(const float4*)&Vm[base];
        } else {
            kv = make_float4(0.f, 0.f, 0.f, 0.f);
            vv = kv;
        }
        Ks[r][c + 0] = kv.x; Ks[r][c + 1] = kv.y;
        Ks[r][c + 2] = kv.z; Ks[r][c + 3] = kv.w;
        *(float4*)&Vs[r][c] = vv;
    }
    __syncthreads();

    const int w = tid >> 5;
    const int l = tid & 31;
    const float scale = 0.125f;

    for (int qi = w; qi < QB; qi += 8) {
        const int q = q0 + qi;
        const int kr0 = qi + l;
        const int kr1 = qi + l + 32;
        float s0 = 0.f, s1 = 0.f;
#pragma unroll 16
        for (int d = 0; d < 64; d++) {
            float qd = Qs[qi][d];
            s0 += qd * Ks[kr0][d];
            s1 += qd * Ks[kr1][d];
        }
        s0 *= scale; s1 *= scale;
        const int j0 = q - HW + l;
        const int j1 = j0 + 32;
        if (j0 < 0 || j0 >= Tn) s0 = -INFINITY;
        if (j1 >= Tn)           s1 = -INFINITY;

        float m = fmaxf(s0, s1);
#pragma unroll
        for (int off = 16; off; off >>= 1)
            m = fmaxf(m, __shfl_xor_sync(0xffffffffu, m, off));
        float p0 = __expf(s0 - m);
        float p1 = __expf(s1 - m);
        float sum = p0 + p1;
#pragma unroll
        for (int off = 16; off; off >>= 1)
            sum += __shfl_xor_sync(0xffffffffu, sum, off);

        Ps[w][l] = p0;
        Ps[w][l + 32] = p1;
        __syncwarp();

        const float inv = 1.0f / sum;
        float acc0 = 0.f, acc1 = 0.f;
#pragma unroll 8
        for (int t = 0; t < 64; t++) {
            float pr = Ps[w][t];
            acc0 += pr * Vs[qi + t][l];
            acc1 += pr * Vs[qi + t][l + 32];
        }
        size_t ob = ((size_t)(b * Tn + q)) * Cn + h * 64;
        float v0 = acc0 * inv, v1 = acc1 * inv;
        __nv_bfloat16 h0 = __float2bfloat16_rn(v0);
        __nv_bfloat16 h1 = __float2bfloat16_rn(v1);
        Oh[ob + l]      = h0;
        Oh[ob + l + 32] = h1;
        Ol[ob + l]      = __float2bfloat16_rn(v0 - __bfloat162float(h0));
        Ol[ob + l + 32] = __float2bfloat16_rn(v1 - __bfloat162float(h1));
        __syncwarp();
    }
}

// ---------------------------------------------------------------------------
extern "C" void kernel_launch(void* const* d_in, const int* in_sizes, int n_in,
                              void* d_out, int out_size)
{
    const float* x   = (const float*)d_in[0];
    const float* q_w = (const float*)d_in[1];
    const float* q_b = (const float*)d_in[2];
    const float* k_w = (const float*)d_in[3];
    const float* k_b = (const float*)d_in[4];
    const float* v_w = (const float*)d_in[5];
    const float* v_b = (const float*)d_in[6];
    const float* o_w = (const float*)d_in[7];
    const float* o_b = (const float*)d_in[8];
    float* out = (float*)d_out;

    float *gq, *gk, *gv;
    __nv_bfloat16 *gxh, *gxl, *gwh, *gwl, *gah, *gal;
    cudaGetSymbolAddress((void**)&gq, g_q);
    cudaGetSymbolAddress((void**)&gk, g_k);
    cudaGetSymbolAddress((void**)&gv, g_v);
    cudaGetSymbolAddress((void**)&gxh, g_xh);
    cudaGetSymbolAddress((void**)&gxl, g_xl);
    cudaGetSymbolAddress((void**)&gwh, g_wh);
    cudaGetSymbolAddress((void**)&gwl, g_wl);
    cudaGetSymbolAddress((void**)&gah, g_ah);
    cudaGetSymbolAddress((void**)&gal, g_al);

    static bool attr_done = false;
    if (!attr_done) {
        cudaFuncSetAttribute(gemm_bf16x3,
                             cudaFuncAttributeMaxDynamicSharedMemorySize, SM_TOTAL);
        attr_done = true;
    }

    const int WN = Cn * Cn;       // 1M
    convert_hilo<<<Mn * Cn / 1024, 256>>>(x, gxh, gxl, Mn * Cn);
    convert_hilo<<<WN / 1024, 256>>>(q_w, gwh,          gwl,          WN);
    convert_hilo<<<WN / 1024, 256>>>(k_w, gwh + WN,     gwl + WN,     WN);
    convert_hilo<<<WN / 1024, 256>>>(v_w, gwh + 2 * WN, gwl + 2 * WN, WN);

    dim3 qkv_grid(Cn / 128, Mn / 128, 3);   // (8, 32, 3)
    gemm_bf16x3<<<qkv_grid, 256, SM_TOTAL>>>(gxh, gxl, gwh, gwl,
                                             q_b, k_b, v_b, gq, gk, gv);

    dim3 attn_grid(Tn / QB, Bn * 16);       // (128, 32)
    attn_win<<<attn_grid, 256>>>(gq, gk, gv, gah, gal);

    convert_hilo<<<WN / 1024, 256>>>(o_w, gwh, gwl, WN);

    dim3 o_grid(Cn / 128, Mn / 128, 1);
    gemm_bf16x3<<<o_grid, 256, SM_TOTAL>>>(gah, gal, gwh, gwl,
                                           o_b, o_b, o_b, out, out, out);
}

// round 4
// speedup vs baseline: 3.9248x; 1.5980x over previous
#include <cuda_runtime.h>
#include <cuda_fp16.h>
#include <cmath>
#include <cstdint>

// Problem constants
constexpr int Bn = 2;
constexpr int Tn = 2048;
constexpr int Cn = 1024;
constexpr int Mn = Bn * Tn;   // 4096
constexpr int WN = Cn * Cn;

// ---------------------------------------------------------------------------
// Scratch (device globals -- no allocation allowed)
// ---------------------------------------------------------------------------
__device__ __align__(256) half g_xh[Mn * Cn];
__device__ __align__(256) half g_wh[4 * WN];
__device__ __align__(256) half g_wl[4 * WN];
__device__ __align__(256) half g_qh[Mn * Cn];
__device__ __align__(256) half g_ql[Mn * Cn];
__device__ __align__(256) half g_kh[Mn * Cn];
__device__ __align__(256) half g_kl[Mn * Cn];
__device__ __align__(256) half g_vh[Mn * Cn];
__device__ __align__(256) half g_vl[Mn * Cn];
__device__ __align__(256) half g_ao[Mn * Cn];

// ---------------------------------------------------------------------------
// PTX helpers (base ISA: cp.async / ldmatrix / mma.sync)
// ---------------------------------------------------------------------------
__device__ __forceinline__ uint32_t smem_u32(const void* p) {
    uint32_t a;
    asm("{ .reg .u64 t; cvta.to.shared.u64 t, %1; cvt.u32.u64 %0, t; }"
        : "=r"(a) : "l"(p));
    return a;
}
__device__ __forceinline__ void cp16(uint32_t s, const void* g) {
    asm volatile("cp.async.cg.shared.global [%0], [%1], 16;" :: "r"(s), "l"(g));
}
__device__ __forceinline__ void ldm_x4(uint32_t& r0, uint32_t& r1,
                                       uint32_t& r2, uint32_t& r3, uint32_t a) {
    asm volatile("ldmatrix.sync.aligned.m8n8.x4.shared.b16 {%0,%1,%2,%3}, [%4];"
                 : "=r"(r0), "=r"(r1), "=r"(r2), "=r"(r3) : "r"(a));
}
__device__ __forceinline__ void ldm_x4_t(uint32_t& r0, uint32_t& r1,
                                         uint32_t& r2, uint32_t& r3, uint32_t a) {
    asm volatile("ldmatrix.sync.aligned.m8n8.x4.trans.shared.b16 {%0,%1,%2,%3}, [%4];"
                 : "=r"(r0), "=r"(r1), "=r"(r2), "=r"(r3) : "r"(a));
}
__device__ __forceinline__ void mma_f16(float* c, const uint32_t* a,
                                        const uint32_t* b) {
    asm volatile(
        "mma.sync.aligned.m16n8k16.row.col.f32.f16.f16.f32 "
        "{%0,%1,%2,%3}, {%4,%5,%6,%7}, {%8,%9}, {%0,%1,%2,%3};"
        : "+f"(c[0]), "+f"(c[1]), "+f"(c[2]), "+f"(c[3])
        : "r"(a[0]), "r"(a[1]), "r"(a[2]), "r"(a[3]), "r"(b[0]), "r"(b[1]));
}
__device__ __forceinline__ uint32_t packh2(float x, float y) {
    half2 h = __floats2half2_rn(x, y);
    return *reinterpret_cast<uint32_t*>(&h);
}

// ---------------------------------------------------------------------------
// fp16 2-pass GEMM:  out[m][n] = sum_k A[m][k]*W[n][k] + bias[n]
// A ~ ah only (dropped a_lo: err ~2^-11 stat.), W ~ wh + wl.
// 128x128 tile, BK=32, 256 threads (8 warps 2x4), warp tile 64x32.
// 3-stage cp.async pipeline, 24KB/stage. blockIdx.z = QKV slice.
// HILO epilogue emits fp16 hi+lo (for attention inputs); else fp32+bias.
// ---------------------------------------------------------------------------
constexpr int GBK = 32;
constexpr int KITERS = Cn / GBK;            // 32
constexpr int TIL = 128 * GBK * 2;          // 8192 bytes
constexpr int GSTAGE = 3 * TIL;             // Ah,Bh,Bl = 24 KB
constexpr int GSM_TOTAL = 3 * GSTAGE;       // 72 KB

template <bool HILO>
__global__ void __launch_bounds__(256) gemm_f16x2(
    const half* __restrict__ a,
    const half* __restrict__ wh, const half* __restrict__ wl,
    const float* __restrict__ b0, const float* __restrict__ b1, const float* __restrict__ b2,
    half* oh0, half* ol0, half* oh1, half* ol1, half* oh2, half* ol2,
    float* of)
{
    extern __shared__ char smem[];
    const uint32_t sb = smem_u32(smem);
    const int tid = threadIdx.x;
    const int z = blockIdx.z;
    const int m0 = blockIdx.y * 128;
    const int n0 = blockIdx.x * 128;

    const half* Bh = wh + (size_t)z * WN;
    const half* Bl = wl + (size_t)z * WN;
    const float* bias = (z == 0) ? b0 : (z == 1) ? b1 : b2;
    half* oh = (z == 0) ? oh0 : (z == 1) ? oh1 : oh2;
    half* ol = (z == 0) ? ol0 : (z == 1) ? ol1 : ol2;

    const int lane = tid & 31;
    const int wid = tid >> 5;
    const int wm = wid >> 2;
    const int wn = wid & 3;

    const int lrow0 = tid >> 2;
    const int lrow1 = lrow0 + 64;
    const int lc = tid & 3;
    const uint32_t soff0 = (uint32_t)(lrow0 * 64 + ((lc ^ ((lrow0 >> 1) & 3)) << 4));
    const uint32_t soff1 = (uint32_t)(lrow1 * 64 + ((lc ^ ((lrow1 >> 1) & 3)) << 4));

    auto load_stage = [&](int it, int s) {
        const int k0 = it * GBK;
        const uint32_t st = sb + s * GSTAGE;
        size_t ga0 = (size_t)(m0 + lrow0) * Cn + k0 + lc * 8;
        size_t ga1 = (size_t)(m0 + lrow1) * Cn + k0 + lc * 8;
        size_t gb0 = (size_t)(n0 + lrow0) * Cn + k0 + lc * 8;
        size_t gb1 = (size_t)(n0 + lrow1) * Cn + k0 + lc * 8;
        cp16(st + soff0,           a + ga0);
        cp16(st + soff1,           a + ga1);
        cp16(st + TIL + soff0,     Bh + gb0);
        cp16(st + TIL + soff1,     Bh + gb1);
        cp16(st + 2 * TIL + soff0, Bl + gb0);
        cp16(st + 2 * TIL + soff1, Bl + gb1);
        asm volatile("cp.async.commit_group;" ::: "memory");
    };

    const int arow = wm * 64 + (lane & 15);
    const int brow = wn * 32 + (lane & 7) + ((lane >> 4) << 3);

    float acc[4][4][4];
#pragma unroll
    for (int i = 0; i < 4; i++)
#pragma unroll
        for (int j = 0; j < 4; j++)
#pragma unroll
            for (int r = 0; r < 4; r++) acc[i][j][r] = 0.0f;

    load_stage(0, 0);
    load_stage(1, 1);

    for (int it = 0; it < KITERS; it++) {
        if (it + 2 < KITERS) load_stage(it + 2, (it + 2) % 3);
        const int rem = KITERS - 1 - it;
        if (rem >= 2)      asm volatile("cp.async.wait_group 2;" ::: "memory");
        else if (rem == 1) asm volatile("cp.async.wait_group 1;" ::: "memory");
        else               asm volatile("cp.async.wait_group 0;" ::: "memory");
        __syncthreads();

        const uint32_t st = sb + (it % 3) * GSTAGE;
#pragma unroll
        for (int ks = 0; ks < 2; ks++) {
            uint32_t fah[4][4], fbh[4][2], fbl[4][2];
            const int akc = ks * 2 + (lane >> 4);
#pragma unroll
            for (int mi = 0; mi < 4; mi++) {
                int row = arow + mi * 16;
                uint32_t off = (uint32_t)(row * 64 + ((akc ^ ((row >> 1) & 3)) << 4));
                ldm_x4(fah[mi][0], fah[mi][1], fah[mi][2], fah[mi][3], st + off);
            }
            const int bkc = ks * 2 + ((lane >> 3) & 1);
#pragma unroll
            for (int p = 0; p < 2; p++) {
                int row = brow + p * 16;
                uint32_t off = (uint32_t)(row * 64 + ((bkc ^ ((row >> 1) & 3)) << 4));
                ldm_x4(fbh[2 * p][0], fbh[2 * p][1], fbh[2 * p + 1][0], fbh[2 * p + 1][1],
                       st + TIL + off);
                ldm_x4(fbl[2 * p][0], fbl[2 * p][1], fbl[2 * p + 1][0], fbl[2 * p + 1][1],
                       st + 2 * TIL + off);
            }
#pragma unroll
            for (int mi = 0; mi < 4; mi++)
#pragma unroll
                for (int ni = 0; ni < 4; ni++) {
                    mma_f16(acc[mi][ni], fah[mi], fbh[ni]);
                    mma_f16(acc[mi][ni], fah[mi], fbl[ni]);
                }
        }
        __syncthreads();
    }

    // epilogue
#pragma unroll
    for (int mi = 0; mi < 4; mi++) {
#pragma unroll
        for (int hh = 0; hh < 2; hh++) {
            int row = m0 + wm * 64 + mi * 16 + (lane >> 2) + hh * 8;
#pragma unroll
            for (int ni = 0; ni < 4; ni++) {
                int col = n0 + wn * 32 + ni * 8 + (lane & 3) * 2;
                float vx = acc[mi][ni][hh * 2 + 0] + bias[col];
                float vy = acc[mi][ni][hh * 2 + 1] + bias[col + 1];
                if (HILO) {
                    half2 hp = __floats2half2_rn(vx, vy);
                    half2 lp = __floats2half2_rn(vx - __half2float(hp.x),
                                                 vy - __half2float(hp.y));
                    *(half2*)&oh[(size_t)row * Cn + col] = hp;
                    *(half2*)&ol[(size_t)row * Cn + col] = lp;
                } else {
                    float2 o; o.x = vx; o.y = vy;
                    *(float2*)&of[(size_t)row * Cn + col] = o;
                }
            }
        }
    }
}

// ---------------------------------------------------------------------------
// Converters
// ---------------------------------------------------------------------------
__global__ void __launch_bounds__(256) convert_x(
    const float* __restrict__ in, half* __restrict__ hi, int n)
{
    int i = (blockIdx.x * 256 + threadIdx.x) * 4;
    if (i >= n) return;
    float4 v = *(const float4*)&in[i];
    *(half2*)&hi[i]     = __floats2half2_rn(v.x, v.y);
    *(half2*)&hi[i + 2] = __floats2half2_rn(v.z, v.w);
}

__global__ void __launch_bounds__(256) convert_w4(
    const float* __restrict__ w0, const float* __restrict__ w1,
    const float* __restrict__ w2, const float* __restrict__ w3,
    half* __restrict__ wh, half* __restrict__ wl)
{
    const int z = blockIdx.y;
    const float* w = (z == 0) ? w0 : (z == 1) ? w1 : (z == 2) ? w2 : w3;
    size_t base = (size_t)z * WN;
    int i = (blockIdx.x * 256 + threadIdx.x) * 4;
    float4 v = *(const float4*)&w[i];
    half2 h0 = __floats2half2_rn(v.x, v.y);
    half2 h1 = __floats2half2_rn(v.z, v.w);
    *(half2*)&wh[base + i]     = h0;
    *(half2*)&wh[base + i + 2] = h1;
    *(half2*)&wl[base + i] =
        __floats2half2_rn(v.x - __half2float(h0.x), v.y - __half2float(h0.y));
    *(half2*)&wl[base + i + 2] =
        __floats2half2_rn(v.z - __half2float(h1.x), v.w - __half2float(h1.y));
}

// ---------------------------------------------------------------------------
// MMA band attention. Block = 64 queries of one (b,h); keys [q0-32, q0+96).
// S = Q K^T  fp16 hi/lo 3-pass; fp32 softmax; O = P V fp16 hi/lo 3-pass with
// P frags rebuilt from S accumulators (register reuse). 8 warps: 4 m-tiles
// (16 rows) x 2 key-halves (64 keys). Band-dead frags skip mma + exp.
// ---------------------------------------------------------------------------
constexpr int ASM_QH = 0;
constexpr int ASM_QL = 8192;
constexpr int ASM_KH = 16384;
constexpr int ASM_KL = 32768;
constexpr int ASM_VH = 49152;
constexpr int ASM_VL = 65536;
constexpr int ASM_TOTAL = 81920;

__device__ __forceinline__ uint32_t swz(int row, int chunk) {
    return (uint32_t)(row * 128 + ((chunk ^ (row & 7)) << 4));
}

__global__ void __launch_bounds__(256) attn_mma(
    const half* __restrict__ qh, const half* __restrict__ ql,
    const half* __restrict__ kh, const half* __restrict__ kl,
    const half* __restrict__ vh, const half* __restrict__ vl,
    half* __restrict__ ao)
{
    extern __shared__ char smem[];
    const uint32_t sb = smem_u32(smem);
    __shared__ float redmax[2][64];
    __shared__ float redsum[2][64];

    const int tid = threadIdx.x;
    const int lane = tid & 31;
    const int wid = tid >> 5;
    const int wm = wid >> 1;        // 0..3 : rows wm*16..+15
    const int wn2 = wid & 1;        // key half
    const int bh = blockIdx.y;
    const int b = bh >> 4;
    const int h = bh & 15;
    const int q0 = blockIdx.x * 64;

    // ---- stage Q (64 rows) and K/V (128 rows) hi/lo, swizzled 128B rows ----
    for (int id = tid; id < 64 * 8; id += 256) {
        int r = id >> 3, c = id & 7;
        uint32_t so = swz(r, c);
        size_t g = ((size_t)(b * Tn + q0 + r)) * Cn + h * 64 + c * 8;
        cp16(sb + ASM_QH + so, qh + g);
        cp16(sb + ASM_QL + so, ql + g);
    }
    for (int id = tid; id < 128 * 8; id += 256) {
        int r = id >> 3, c = id & 7;
        int tok = q0 - 32 + r;
        tok = tok < 0 ? 0 : (tok >= Tn ? Tn - 1 : tok);
        uint32_t so = swz(r, c);
        size_t g = ((size_t)(b * Tn + tok)) * Cn + h * 64 + c * 8;
        cp16(sb + ASM_KH + so, kh + g);
        cp16(sb + ASM_KL + so, kl + g);
        cp16(sb + ASM_VH + so, vh + g);
        cp16(sb + ASM_VL + so, vl + g);
    }
    asm volatile("cp.async.commit_group;" ::: "memory");
    asm volatile("cp.async.wait_group 0;" ::: "memory");
    __syncthreads();

    const int bandlo = wm * 16;
    const int bandhi = wm * 16 + 80;
    auto live = [&](int nt) {
        int c0 = wn2 * 64 + nt * 8;
        return (c0 + 8 > bandlo) && (c0 < bandhi);
    };

    // ---- S = Q K^T (3-pass) ----
    float sacc[8][4];
#pragma unroll
    for (int i = 0; i < 8; i++)
#pragma unroll
        for (int j = 0; j < 4; j++) sacc[i][j] = 0.0f;

    const int aQrow = wm * 16 + (lane & 15);
    const int aQc = lane >> 4;
    const int bKrow = wn2 * 64 + (lane & 7) + ((lane >> 4) << 3);
    const int bKc = (lane >> 3) & 1;

#pragma unroll
    for (int kc = 0; kc < 4; kc++) {
        uint32_t fah[4], fal[4];
        uint32_t aoff = swz(aQrow, kc * 2 + aQc);
        ldm_x4(fah[0], fah[1], fah[2], fah[3], sb + ASM_QH + aoff);
        ldm_x4(fal[0], fal[1], fal[2], fal[3], sb + ASM_QL + aoff);
        uint32_t fbh[8][2], fbl[8][2];
#pragma unroll
        for (int p = 0; p < 4; p++) {
            if (live(2 * p) || live(2 * p + 1)) {
                uint32_t off = swz(bKrow + p * 16, kc * 2 + bKc);
                ldm_x4(fbh[2 * p][0], fbh[2 * p][1], fbh[2 * p + 1][0], fbh[2 * p + 1][1],
                       sb + ASM_KH + off);
                ldm_x4(fbl[2 * p][0], fbl[2 * p][1], fbl[2 * p + 1][0], fbl[2 * p + 1][1],
                       sb + ASM_KL + off);
            }
        }
#pragma unroll
        for (int nt = 0; nt < 8; nt++) {
            if (live(nt)) {
                mma_f16(sacc[nt], fah, fbh[nt]);
                mma_f16(sacc[nt], fah, fbl[nt]);
                mma_f16(sacc[nt], fal, fbh[nt]);
            }
        }
    }

    // ---- mask + scale + row max ----
    const int r0 = lane >> 2;
    const int qg0 = q0 + wm * 16 + r0;
    const int qg1 = qg0 + 8;
    float mx[2] = {-1e30f, -1e30f};
#pragma unroll
    for (int nt = 0; nt < 8; nt++) {
        if (live(nt)) {
            int cb = wn2 * 64 + nt * 8 + (lane & 3) * 2;
#pragma unroll
            for (int i = 0; i < 4; i++) {
                int qq = (i < 2) ? qg0 : qg1;
                int jj = q0 - 32 + cb + (i & 1);
                bool ok = (jj >= qq - 32) && (jj < qq + 32) && (jj >= 0) && (jj < Tn);
                float s = ok ? sacc[nt][i] * 0.125f : -1e30f;
                sacc[nt][i] = s;
                mx[i >> 1] = fmaxf(mx[i >> 1], s);
            }
        } else {
#pragma unroll
            for (int i = 0; i < 4; i++) sacc[nt][i] = -1e30f;
        }
    }
#pragma unroll
    for (int j = 0; j < 2; j++) {
        mx[j] = fmaxf(mx[j], __shfl_xor_sync(0xffffffffu, mx[j], 1));
        mx[j] = fmaxf(mx[j], __shfl_xor_sync(0xffffffffu, mx[j], 2));
    }
    if ((lane & 3) == 0) {
        redmax[wn2][wm * 16 + r0] = mx[0];
        redmax[wn2][wm * 16 + r0 + 8] = mx[1];
    }
    __syncthreads();
    float M0 = fmaxf(redmax[0][wm * 16 + r0], redmax[1][wm * 16 + r0]);
    float M1 = fmaxf(redmax[0][wm * 16 + r0 + 8], redmax[1][wm * 16 + r0 + 8]);

    // ---- exp + row sum ----
    float sm[2] = {0.0f, 0.0f};
#pragma unroll
    for (int nt = 0; nt < 8; nt++) {
        if (live(nt)) {
#pragma unroll
            for (int i = 0; i < 4; i++) {
                float p = __expf(sacc[nt][i] - ((i < 2) ? M0 : M1));
                sacc[nt][i] = p;
                sm[i >> 1] += p;
            }
        } else {
#pragma unroll
            for (int i = 0; i < 4; i++) sacc[nt][i] = 0.0f;
        }
    }
#pragma unroll
    for (int j = 0; j < 2; j++) {
        sm[j] += __shfl_xor_sync(0xffffffffu, sm[j], 1);
        sm[j] += __shfl_xor_sync(0xffffffffu, sm[j], 2);
    }
    if ((lane & 3) == 0) {
        redsum[wn2][wm * 16 + r0] = sm[0];
        redsum[wn2][wm * 16 + r0 + 8] = sm[1];
    }
    __syncthreads();
    const float inv0 = 1.0f / (redsum[0][wm * 16 + r0] + redsum[1][wm * 16 + r0]);
    const float inv1 = 1.0f / (redsum[0][wm * 16 + r0 + 8] + redsum[1][wm * 16 + r0 + 8]);

    // ---- O = P V (3-pass), partial over this warp's 64 keys ----
    float oacc[8][4];
#pragma unroll
    for (int i = 0; i < 8; i++)
#pragma unroll
        for (int j = 0; j < 4; j++) oacc[i][j] = 0.0f;

    const int vrow = wn2 * 64 + ((lane >> 3) & 1) * 8 + (lane & 7);
    const int vc = lane >> 4;

#pragma unroll
    for (int kc = 0; kc < 4; kc++) {
        const int nt0 = 2 * kc, nt1 = 2 * kc + 1;
        if (!(live(nt0) || live(nt1))) continue;
        // P frags (hi/lo) from S accumulators
        uint32_t pah[4], pal[4];
        float ps[8] = {sacc[nt0][0], sacc[nt0][1], sacc[nt0][2], sacc[nt0][3],
                       sacc[nt1][0], sacc[nt1][1], sacc[nt1][2], sacc[nt1][3]};
        float pl[8];
#pragma unroll
        for (int i = 0; i < 8; i++) {
            half hv = __float2half_rn(ps[i]);
            pl[i] = ps[i] - __half2float(hv);
        }
        pah[0] = packh2(ps[0], ps[1]); pah[1] = packh2(ps[2], ps[3]);
        pah[2] = packh2(ps[4], ps[5]); pah[3] = packh2(ps[6], ps[7]);
        pal[0] = packh2(pl[0], pl[1]); pal[1] = packh2(pl[2], pl[3]);
        pal[2] = packh2(pl[4], pl[5]); pal[3] = packh2(pl[6], pl[7]);
        // V frags via ldmatrix.trans
        uint32_t fvh[8][2], fvl[8][2];
#pragma unroll
        for (int p = 0; p < 4; p++) {
            uint32_t off = swz(vrow + kc * 16, p * 2 + vc);
            ldm_x4_t(fvh[2 * p][0], fvh[2 * p][1], fvh[2 * p + 1][0], fvh[2 * p + 1][1],
                     sb + ASM_VH + off);
            ldm_x4_t(fvl[2 * p][0], fvl[2 * p][1], fvl[2 * p + 1][0], fvl[2 * p + 1][1],
                     sb + ASM_VL + off);
        }
#pragma unroll
        for (int nd = 0; nd < 8; nd++) {
            mma_f16(oacc[nd], pah, fvh[nd]);
            mma_f16(oacc[nd], pah, fvl[nd]);
            mma_f16(oacc[nd], pal, fvh[nd]);
        }
    }

    // ---- reduce across the 2 key-halves, normalize, store fp16 hi ----
    float* Obuf = (float*)smem;   // overlays Q region (16 KB), Q dead now
    if (wn2 == 0) {
#pragma unroll
        for (int nd = 0; nd < 8; nd++)
#pragma unroll
            for (int i = 0; i < 4; i++) {
                int r = ((i < 2) ? r0 : r0 + 8);
                int d = nd * 8 + (lane & 3) * 2 + (i & 1);
                Obuf[wm * 1024 + r * 64 + d] = oacc[nd][i];
            }
    }
    __syncthreads();
    if (wn2 == 1) {
#pragma unroll
        for (int nd = 0; nd < 8; nd++) {
            int d0 = nd * 8 + (lane & 3) * 2;
            float o00 = (oacc[nd][0] + Obuf[wm * 1024 + r0 * 64 + d0]) * inv0;
            float o01 = (oacc[nd][1] + Obuf[wm * 1024 + r0 * 64 + d0 + 1]) * inv0;
            float o10 = (oacc[nd][2] + Obuf[wm * 1024 + (r0 + 8) * 64 + d0]) * inv1;
            float o11 = (oacc[nd][3] + Obuf[wm * 1024 + (r0 + 8) * 64 + d0 + 1]) * inv1;
            size_t g0 = ((size_t)(b * Tn + qg0)) * Cn + h * 64 + d0;
            size_t g1 = ((size_t)(b * Tn + qg1)) * Cn + h * 64 + d0;
            *(half2*)&ao[g0] = __floats2half2_rn(o00, o01);
            *(half2*)&ao[g1] = __floats2half2_rn(o10, o11);
        }
    }
}

// ---------------------------------------------------------------------------
extern "C" void kernel_launch(void* const* d_in, const int* in_sizes, int n_in,
                              void* d_out, int out_size)
{
    const float* x   = (const float*)d_in[0];
    const float* q_w = (const float*)d_in[1];
    const float* q_b = (const float*)d_in[2];
    const float* k_w = (const float*)d_in[3];
    const float* k_b = (const float*)d_in[4];
    const float* v_w = (const float*)d_in[5];
    const float* v_b = (const float*)d_in[6];
    const float* o_w = (const float*)d_in[7];
    const float* o_b = (const float*)d_in[8];
    float* out = (float*)d_out;

    half *xh, *wh, *wl, *pqh, *pql, *pkh, *pkl, *pvh, *pvl, *pao;
    cudaGetSymbolAddress((void**)&xh, g_xh);
    cudaGetSymbolAddress((void**)&wh, g_wh);
    cudaGetSymbolAddress((void**)&wl, g_wl);
    cudaGetSymbolAddress((void**)&pqh, g_qh);
    cudaGetSymbolAddress((void**)&pql, g_ql);
    cudaGetSymbolAddress((void**)&pkh, g_kh);
    cudaGetSymbolAddress((void**)&pkl, g_kl);
    cudaGetSymbolAddress((void**)&pvh, g_vh);
    cudaGetSymbolAddress((void**)&pvl, g_vl);
    cudaGetSymbolAddress((void**)&pao, g_ao);

    cudaFuncSetAttribute(gemm_f16x2<true>,
                         cudaFuncAttributeMaxDynamicSharedMemorySize, GSM_TOTAL);
    cudaFuncSetAttribute(gemm_f16x2<false>,
                         cudaFuncAttributeMaxDynamicSharedMemorySize, GSM_TOTAL);
    cudaFuncSetAttribute(attn_mma,
                         cudaFuncAttributeMaxDynamicSharedMemorySize, ASM_TOTAL);

    convert_x<<<Mn * Cn / 1024, 256>>>(x, xh, Mn * Cn);
    dim3 wgrid(WN / 1024, 4);
    convert_w4<<<wgrid, 256>>>(q_w, k_w, v_w, o_w, wh, wl);

    dim3 qkv_grid(Cn / 128, Mn / 128, 3);
    gemm_f16x2<true><<<qkv_grid, 256, GSM_TOTAL>>>(
        xh, wh, wl, q_b, k_b, v_b,
        pqh, pql, pkh, pkl, pvh, pvl, nullptr);

    dim3 attn_grid(Tn / 64, Bn * 16);
    attn_mma<<<attn_grid, 256, ASM_TOTAL>>>(pqh, pql, pkh, pkl, pvh, pvl, pao);

    dim3 o_grid(Cn / 128, Mn / 128, 1);
    gemm_f16x2<false><<<o_grid, 256, GSM_TOTAL>>>(
        pao, wh + 3 * (size_t)WN, wl + 3 * (size_t)WN, o_b, o_b, o_b,
        nullptr, nullptr, nullptr, nullptr, nullptr, nullptr, out);
}

// round 5
// speedup vs baseline: 5.3922x; 1.3739x over previous
#include <cuda_runtime.h>
#include <cuda_fp16.h>
#include <cmath>
#include <cstdint>

// Problem constants
constexpr int Bn = 2;
constexpr int Tn = 2048;
constexpr int Cn = 1024;
constexpr int Mn = Bn * Tn;   // 4096
constexpr int WN = Cn * Cn;

// ---------------------------------------------------------------------------
// Scratch (device globals -- no allocation allowed)
// ---------------------------------------------------------------------------
__device__ __align__(256) half g_xh[Mn * Cn];
__device__ __align__(256) half g_wh[4 * WN];     // q,k,v,o weights fp16-hi
__device__ __align__(256) half g_wl[WN];         // o weight fp16-lo only
__device__ __align__(256) half g_qh[Mn * Cn];
__device__ __align__(256) half g_kh[Mn * Cn];
__device__ __align__(256) half g_vh[Mn * Cn];
__device__ __align__(256) half g_ao[Mn * Cn];

// ---------------------------------------------------------------------------
// PTX helpers (base ISA: cp.async / ldmatrix / mma.sync)
// ---------------------------------------------------------------------------
__device__ __forceinline__ uint32_t smem_u32(const void* p) {
    uint32_t a;
    asm("{ .reg .u64 t; cvta.to.shared.u64 t, %1; cvt.u32.u64 %0, t; }"
        : "=r"(a) : "l"(p));
    return a;
}
__device__ __forceinline__ void cp16(uint32_t s, const void* g) {
    asm volatile("cp.async.cg.shared.global [%0], [%1], 16;" :: "r"(s), "l"(g));
}
__device__ __forceinline__ void ldm_x4(uint32_t& r0, uint32_t& r1,
                                       uint32_t& r2, uint32_t& r3, uint32_t a) {
    asm volatile("ldmatrix.sync.aligned.m8n8.x4.shared.b16 {%0,%1,%2,%3}, [%4];"
                 : "=r"(r0), "=r"(r1), "=r"(r2), "=r"(r3) : "r"(a));
}
__device__ __forceinline__ void ldm_x4_t(uint32_t& r0, uint32_t& r1,
                                         uint32_t& r2, uint32_t& r3, uint32_t a) {
    asm volatile("ldmatrix.sync.aligned.m8n8.x4.trans.shared.b16 {%0,%1,%2,%3}, [%4];"
                 : "=r"(r0), "=r"(r1), "=r"(r2), "=r"(r3) : "r"(a));
}
__device__ __forceinline__ void mma_f16(float* c, const uint32_t* a,
                                        const uint32_t* b) {
    asm volatile(
        "mma.sync.aligned.m16n8k16.row.col.f32.f16.f16.f32 "
        "{%0,%1,%2,%3}, {%4,%5,%6,%7}, {%8,%9}, {%0,%1,%2,%3};"
        : "+f"(c[0]), "+f"(c[1]), "+f"(c[2]), "+f"(c[3])
        : "r"(a[0]), "r"(a[1]), "r"(a[2]), "r"(a[3]), "r"(b[0]), "r"(b[1]));
}
__device__ __forceinline__ uint32_t packh2(float x, float y) {
    half2 h = __floats2half2_rn(x, y);
    return *reinterpret_cast<uint32_t*>(&h);
}

// ---------------------------------------------------------------------------
// fp16 GEMM:  out[m][n] = sum_k A[m][k]*W[n][k] + bias[n]
// PASSES=1: W ~ wh only.  PASSES=2: W ~ wh + wl (hi/lo split).
// 128x128 tile, BK=32, 256 threads (8 warps 2x4), warp tile 64x32.
// 3-stage cp.async pipeline. blockIdx.z selects QKV slice.
// F16OUT: fp16 output (attention inputs); else fp32 + bias to of.
// ---------------------------------------------------------------------------
constexpr int GBK = 32;
constexpr int KITERS = Cn / GBK;            // 32
constexpr int TIL = 128 * GBK * 2;          // 8192 bytes

template <int PASSES, bool F16OUT>
__global__ void __launch_bounds__(256) gemm_f16(
    const half* __restrict__ a,
    const half* __restrict__ wh, const half* __restrict__ wl,
    const float* __restrict__ b0, const float* __restrict__ b1, const float* __restrict__ b2,
    half* oh0, half* oh1, half* oh2, float* of)
{
    constexpr int STG = (1 + PASSES) * TIL;
    extern __shared__ char smem[];
    const uint32_t sb = smem_u32(smem);
    const int tid = threadIdx.x;
    const int z = blockIdx.z;
    const int m0 = blockIdx.y * 128;
    const int n0 = blockIdx.x * 128;

    const half* Bh = wh + (size_t)z * WN;
    const half* Bl = wl;   // only used when PASSES==2 (z==0)
    const float* bias = (z == 0) ? b0 : (z == 1) ? b1 : b2;
    half* oh = (z == 0) ? oh0 : (z == 1) ? oh1 : oh2;

    const int lane = tid & 31;
    const int wid = tid >> 5;
    const int wm = wid >> 2;
    const int wn = wid & 3;

    const int lrow0 = tid >> 2;
    const int lrow1 = lrow0 + 64;
    const int lc = tid & 3;
    const uint32_t soff0 = (uint32_t)(lrow0 * 64 + ((lc ^ ((lrow0 >> 1) & 3)) << 4));
    const uint32_t soff1 = (uint32_t)(lrow1 * 64 + ((lc ^ ((lrow1 >> 1) & 3)) << 4));

    auto load_stage = [&](int it, int s) {
        const int k0 = it * GBK;
        const uint32_t st = sb + s * STG;
        size_t ga0 = (size_t)(m0 + lrow0) * Cn + k0 + lc * 8;
        size_t ga1 = (size_t)(m0 + lrow1) * Cn + k0 + lc * 8;
        size_t gb0 = (size_t)(n0 + lrow0) * Cn + k0 + lc * 8;
        size_t gb1 = (size_t)(n0 + lrow1) * Cn + k0 + lc * 8;
        cp16(st + soff0,       a + ga0);
        cp16(st + soff1,       a + ga1);
        cp16(st + TIL + soff0, Bh + gb0);
        cp16(st + TIL + soff1, Bh + gb1);
        if (PASSES == 2) {
            cp16(st + 2 * TIL + soff0, Bl + gb0);
            cp16(st + 2 * TIL + soff1, Bl + gb1);
        }
        asm volatile("cp.async.commit_group;" ::: "memory");
    };

    const int arow = wm * 64 + (lane & 15);
    const int brow = wn * 32 + (lane & 7) + ((lane >> 4) << 3);

    float acc[4][4][4];
#pragma unroll
    for (int i = 0; i < 4; i++)
#pragma unroll
        for (int j = 0; j < 4; j++)
#pragma unroll
            for (int r = 0; r < 4; r++) acc[i][j][r] = 0.0f;

    load_stage(0, 0);
    load_stage(1, 1);

    for (int it = 0; it < KITERS; it++) {
        if (it + 2 < KITERS) load_stage(it + 2, (it + 2) % 3);
        const int rem = KITERS - 1 - it;
        if (rem >= 2)      asm volatile("cp.async.wait_group 2;" ::: "memory");
        else if (rem == 1) asm volatile("cp.async.wait_group 1;" ::: "memory");
        else               asm volatile("cp.async.wait_group 0;" ::: "memory");
        __syncthreads();

        const uint32_t st = sb + (it % 3) * STG;
#pragma unroll
        for (int ks = 0; ks < 2; ks++) {
            uint32_t fah[4][4], fbh[4][2], fbl[4][2];
            const int akc = ks * 2 + (lane >> 4);
#pragma unroll
            for (int mi = 0; mi < 4; mi++) {
                int row = arow + mi * 16;
                uint32_t off = (uint32_t)(row * 64 + ((akc ^ ((row >> 1) & 3)) << 4));
                ldm_x4(fah[mi][0], fah[mi][1], fah[mi][2], fah[mi][3], st + off);
            }
            const int bkc = ks * 2 + ((lane >> 3) & 1);
#pragma unroll
            for (int p = 0; p < 2; p++) {
                int row = brow + p * 16;
                uint32_t off = (uint32_t)(row * 64 + ((bkc ^ ((row >> 1) & 3)) << 4));
                ldm_x4(fbh[2 * p][0], fbh[2 * p][1], fbh[2 * p + 1][0], fbh[2 * p + 1][1],
                       st + TIL + off);
                if (PASSES == 2)
                    ldm_x4(fbl[2 * p][0], fbl[2 * p][1], fbl[2 * p + 1][0], fbl[2 * p + 1][1],
                           st + 2 * TIL + off);
            }
#pragma unroll
            for (int mi = 0; mi < 4; mi++)
#pragma unroll
                for (int ni = 0; ni < 4; ni++) {
                    mma_f16(acc[mi][ni], fah[mi], fbh[ni]);
                    if (PASSES == 2) mma_f16(acc[mi][ni], fah[mi], fbl[ni]);
                }
        }
        __syncthreads();
    }

    // epilogue
#pragma unroll
    for (int mi = 0; mi < 4; mi++) {
#pragma unroll
        for (int hh = 0; hh < 2; hh++) {
            int row = m0 + wm * 64 + mi * 16 + (lane >> 2) + hh * 8;
#pragma unroll
            for (int ni = 0; ni < 4; ni++) {
                int col = n0 + wn * 32 + ni * 8 + (lane & 3) * 2;
                float vx = acc[mi][ni][hh * 2 + 0] + bias[col];
                float vy = acc[mi][ni][hh * 2 + 1] + bias[col + 1];
                if (F16OUT) {
                    *(half2*)&oh[(size_t)row * Cn + col] = __floats2half2_rn(vx, vy);
                } else {
                    float2 o; o.x = vx; o.y = vy;
                    *(float2*)&of[(size_t)row * Cn + col] = o;
                }
            }
        }
    }
}

// ---------------------------------------------------------------------------
// Converters
// ---------------------------------------------------------------------------
__global__ void __launch_bounds__(256) convert_x(
    const float* __restrict__ in, half* __restrict__ hi, int n)
{
    int i = (blockIdx.x * 256 + threadIdx.x) * 4;
    if (i >= n) return;
    float4 v = *(const float4*)&in[i];
    *(half2*)&hi[i]     = __floats2half2_rn(v.x, v.y);
    *(half2*)&hi[i + 2] = __floats2half2_rn(v.z, v.w);
}

// wh for all 4 weight slices; wl only for o_w (z==3)
__global__ void __launch_bounds__(256) convert_w4(
    const float* __restrict__ w0, const float* __restrict__ w1,
    const float* __restrict__ w2, const float* __restrict__ w3,
    half* __restrict__ wh, half* __restrict__ wl)
{
    const int z = blockIdx.y;
    const float* w = (z == 0) ? w0 : (z == 1) ? w1 : (z == 2) ? w2 : w3;
    size_t base = (size_t)z * WN;
    int i = (blockIdx.x * 256 + threadIdx.x) * 4;
    float4 v = *(const float4*)&w[i];
    half2 h0 = __floats2half2_rn(v.x, v.y);
    half2 h1 = __floats2half2_rn(v.z, v.w);
    *(half2*)&wh[base + i]     = h0;
    *(half2*)&wh[base + i + 2] = h1;
    if (z == 3) {
        *(half2*)&wl[i] =
            __floats2half2_rn(v.x - __half2float(h0.x), v.y - __half2float(h0.y));
        *(half2*)&wl[i + 2] =
            __floats2half2_rn(v.z - __half2float(h1.x), v.w - __half2float(h1.y));
    }
}

// ---------------------------------------------------------------------------
// MMA band attention. Block = 64 queries of one (b,h); keys [q0-32, q0+96).
// q,k,v are fp16 values (exact): S = Q K^T single-pass is exact in fp32 acc.
// fp32 softmax; O = P V with P split hi/lo (2-pass) for near-exact P.
// 8 warps: 4 m-tiles (16 rows) x 2 key-halves (64 keys). Dead frags skipped.
// ---------------------------------------------------------------------------
constexpr int ASM_QH = 0;          // 8 KB
constexpr int ASM_KH = 8192;       // 16 KB
constexpr int ASM_VH = 24576;      // 16 KB
constexpr int ASM_TOTAL = 40960;

__device__ __forceinline__ uint32_t swz(int row, int chunk) {
    return (uint32_t)(row * 128 + ((chunk ^ (row & 7)) << 4));
}

__global__ void __launch_bounds__(256) attn_mma(
    const half* __restrict__ qh, const half* __restrict__ kh,
    const half* __restrict__ vh, half* __restrict__ ao)
{
    extern __shared__ char smem[];
    const uint32_t sb = smem_u32(smem);
    __shared__ float redmax[2][64];
    __shared__ float redsum[2][64];

    const int tid = threadIdx.x;
    const int lane = tid & 31;
    const int wid = tid >> 5;
    const int wm = wid >> 1;        // 0..3 : rows wm*16..+15
    const int wn2 = wid & 1;        // key half
    const int bh = blockIdx.y;
    const int b = bh >> 4;
    const int h = bh & 15;
    const int q0 = blockIdx.x * 64;

    // ---- stage Q (64 rows) and K/V (128 rows), swizzled 128B rows ----
    for (int id = tid; id < 64 * 8; id += 256) {
        int r = id >> 3, c = id & 7;
        size_t g = ((size_t)(b * Tn + q0 + r)) * Cn + h * 64 + c * 8;
        cp16(sb + ASM_QH + swz(r, c), qh + g);
    }
    for (int id = tid; id < 128 * 8; id += 256) {
        int r = id >> 3, c = id & 7;
        int tok = q0 - 32 + r;
        tok = tok < 0 ? 0 : (tok >= Tn ? Tn - 1 : tok);
        uint32_t so = swz(r, c);
        size_t g = ((size_t)(b * Tn + tok)) * Cn + h * 64 + c * 8;
        cp16(sb + ASM_KH + so, kh + g);
        cp16(sb + ASM_VH + so, vh + g);
    }
    asm volatile("cp.async.commit_group;" ::: "memory");
    asm volatile("cp.async.wait_group 0;" ::: "memory");
    __syncthreads();

    const int bandlo = wm * 16;
    const int bandhi = wm * 16 + 80;
    auto live = [&](int nt) {
        int c0 = wn2 * 64 + nt * 8;
        return (c0 + 8 > bandlo) && (c0 < bandhi);
    };

    // ---- S = Q K^T (single pass, exact) ----
    float sacc[8][4];
#pragma unroll
    for (int i = 0; i < 8; i++)
#pragma unroll
        for (int j = 0; j < 4; j++) sacc[i][j] = 0.0f;

    const int aQrow = wm * 16 + (lane & 15);
    const int aQc = lane >> 4;
    const int bKrow = wn2 * 64 + (lane & 7) + ((lane >> 4) << 3);
    const int bKc = (lane >> 3) & 1;

#pragma unroll
    for (int kc = 0; kc < 4; kc++) {
        uint32_t fah[4];
        ldm_x4(fah[0], fah[1], fah[2], fah[3],
               sb + ASM_QH + swz(aQrow, kc * 2 + aQc));
        uint32_t fbh[8][2];
#pragma unroll
        for (int p = 0; p < 4; p++) {
            if (live(2 * p) || live(2 * p + 1)) {
                uint32_t off = swz(bKrow + p * 16, kc * 2 + bKc);
                ldm_x4(fbh[2 * p][0], fbh[2 * p][1], fbh[2 * p + 1][0], fbh[2 * p + 1][1],
                       sb + ASM_KH + off);
            }
        }
#pragma unroll
        for (int nt = 0; nt < 8; nt++)
            if (live(nt)) mma_f16(sacc[nt], fah, fbh[nt]);
    }

    // ---- mask + scale + row max ----
    const int r0 = lane >> 2;
    const int qg0 = q0 + wm * 16 + r0;
    const int qg1 = qg0 + 8;
    float mx[2] = {-1e30f, -1e30f};
#pragma unroll
    for (int nt = 0; nt < 8; nt++) {
        if (live(nt)) {
            int cb = wn2 * 64 + nt * 8 + (lane & 3) * 2;
#pragma unroll
            for (int i = 0; i < 4; i++) {
                int qq = (i < 2) ? qg0 : qg1;
                int jj = q0 - 32 + cb + (i & 1);
                bool ok = (jj >= qq - 32) && (jj < qq + 32) && (jj >= 0) && (jj < Tn);
                float s = ok ? sacc[nt][i] * 0.125f : -1e30f;
                sacc[nt][i] = s;
                mx[i >> 1] = fmaxf(mx[i >> 1], s);
            }
        } else {
#pragma unroll
            for (int i = 0; i < 4; i++) sacc[nt][i] = -1e30f;
        }
    }
#pragma unroll
    for (int j = 0; j < 2; j++) {
        mx[j] = fmaxf(mx[j], __shfl_xor_sync(0xffffffffu, mx[j], 1));
        mx[j] = fmaxf(mx[j], __shfl_xor_sync(0xffffffffu, mx[j], 2));
    }
    if ((lane & 3) == 0) {
        redmax[wn2][wm * 16 + r0] = mx[0];
        redmax[wn2][wm * 16 + r0 + 8] = mx[1];
    }
    __syncthreads();
    float M0 = fmaxf(redmax[0][wm * 16 + r0], redmax[1][wm * 16 + r0]);
    float M1 = fmaxf(redmax[0][wm * 16 + r0 + 8], redmax[1][wm * 16 + r0 + 8]);

    // ---- exp + row sum ----
    float sm[2] = {0.0f, 0.0f};
#pragma unroll
    for (int nt = 0; nt < 8; nt++) {
        if (live(nt)) {
#pragma unroll
            for (int i = 0; i < 4; i++) {
                float p = __expf(sacc[nt][i] - ((i < 2) ? M0 : M1));
                sacc[nt][i] = p;
                sm[i >> 1] += p;
            }
        } else {
#pragma unroll
            for (int i = 0; i < 4; i++) sacc[nt][i] = 0.0f;
        }
    }
#pragma unroll
    for (int j = 0; j < 2; j++) {
        sm[j] += __shfl_xor_sync(0xffffffffu, sm[j], 1);
        sm[j] += __shfl_xor_sync(0xffffffffu, sm[j], 2);
    }
    if ((lane & 3) == 0) {
        redsum[wn2][wm * 16 + r0] = sm[0];
        redsum[wn2][wm * 16 + r0 + 8] = sm[1];
    }
    __syncthreads();
    const float inv0 = 1.0f / (redsum[0][wm * 16 + r0] + redsum[1][wm * 16 + r0]);
    const float inv1 = 1.0f / (redsum[0][wm * 16 + r0 + 8] + redsum[1][wm * 16 + r0 + 8]);

    // ---- O = P V (P hi/lo 2-pass, V exact), partial over warp's 64 keys ----
    float oacc[8][4];
#pragma unroll
    for (int i = 0; i < 8; i++)
#pragma unroll
        for (int j = 0; j < 4; j++) oacc[i][j] = 0.0f;

    const int vrow = wn2 * 64 + ((lane >> 3) & 1) * 8 + (lane & 7);
    const int vc = lane >> 4;

#pragma unroll
    for (int kc = 0; kc < 4; kc++) {
        const int nt0 = 2 * kc, nt1 = 2 * kc + 1;
        if (!(live(nt0) || live(nt1))) continue;
        uint32_t pah[4], pal[4];
        float ps[8] = {sacc[nt0][0], sacc[nt0][1], sacc[nt0][2], sacc[nt0][3],
                       sacc[nt1][0], sacc[nt1][1], sacc[nt1][2], sacc[nt1][3]};
        float pl[8];
#pragma unroll
        for (int i = 0; i < 8; i++) {
            half hv = __float2half_rn(ps[i]);
            pl[i] = ps[i] - __half2float(hv);
        }
        pah[0] = packh2(ps[0], ps[1]); pah[1] = packh2(ps[2], ps[3]);
        pah[2] = packh2(ps[4], ps[5]); pah[3] = packh2(ps[6], ps[7]);
        pal[0] = packh2(pl[0], pl[1]); pal[1] = packh2(pl[2], pl[3]);
        pal[2] = packh2(pl[4], pl[5]); pal[3] = packh2(pl[6], pl[7]);
        uint32_t fvh[8][2];
#pragma unroll
        for (int p = 0; p < 4; p++) {
            uint32_t off = swz(vrow + kc * 16, p * 2 + vc);
            ldm_x4_t(fvh[2 * p][0], fvh[2 * p][1], fvh[2 * p + 1][0], fvh[2 * p + 1][1],
                     sb + ASM_VH + off);
        }
#pragma unroll
        for (int nd = 0; nd < 8; nd++) {
            mma_f16(oacc[nd], pah, fvh[nd]);
            mma_f16(oacc[nd], pal, fvh[nd]);
        }
    }

    // ---- reduce across the 2 key-halves, normalize, store fp16 ----
    float* Obuf = (float*)smem;   // overlays Q + half of K (both dead: 16 KB)
    if (wn2 == 0) {
#pragma unroll
        for (int nd = 0; nd < 8; nd++)
#pragma unroll
            for (int i = 0; i < 4; i++) {
                int r = ((i < 2) ? r0 : r0 + 8);
                int d = nd * 8 + (lane & 3) * 2 + (i & 1);
                Obuf[wm * 1024 + r * 64 + d] = oacc[nd][i];
            }
    }
    __syncthreads();
    if (wn2 == 1) {
#pragma unroll
        for (int nd = 0; nd < 8; nd++) {
            int d0 = nd * 8 + (lane & 3) * 2;
            float o00 = (oacc[nd][0] + Obuf[wm * 1024 + r0 * 64 + d0]) * inv0;
            float o01 = (oacc[nd][1] + Obuf[wm * 1024 + r0 * 64 + d0 + 1]) * inv0;
            float o10 = (oacc[nd][2] + Obuf[wm * 1024 + (r0 + 8) * 64 + d0]) * inv1;
            float o11 = (oacc[nd][3] + Obuf[wm * 1024 + (r0 + 8) * 64 + d0 + 1]) * inv1;
            size_t g0 = ((size_t)(b * Tn + qg0)) * Cn + h * 64 + d0;
            size_t g1 = ((size_t)(b * Tn + qg1)) * Cn + h * 64 + d0;
            *(half2*)&ao[g0] = __floats2half2_rn(o00, o01);
            *(half2*)&ao[g1] = __floats2half2_rn(o10, o11);
        }
    }
}

// ---------------------------------------------------------------------------
extern "C" void kernel_launch(void* const* d_in, const int* in_sizes, int n_in,
                              void* d_out, int out_size)
{
    const float* x   = (const float*)d_in[0];
    const float* q_w = (const float*)d_in[1];
    const float* q_b = (const float*)d_in[2];
    const float* k_w = (const float*)d_in[3];
    const float* k_b = (const float*)d_in[4];
    const float* v_w = (const float*)d_in[5];
    const float* v_b = (const float*)d_in[6];
    const float* o_w = (const float*)d_in[7];
    const float* o_b = (const float*)d_in[8];
    float* out = (float*)d_out;

    half *xh, *wh, *wl, *pqh, *pkh, *pvh, *pao;
    cudaGetSymbolAddress((void**)&xh, g_xh);
    cudaGetSymbolAddress((void**)&wh, g_wh);
    cudaGetSymbolAddress((void**)&wl, g_wl);
    cudaGetSymbolAddress((void**)&pqh, g_qh);
    cudaGetSymbolAddress((void**)&pkh, g_kh);
    cudaGetSymbolAddress((void**)&pvh, g_vh);
    cudaGetSymbolAddress((void**)&pao, g_ao);

    constexpr int SM_QKV = 3 * 2 * TIL;   // 48 KB (A + Bh, 3 stages)
    constexpr int SM_O   = 3 * 3 * TIL;   // 72 KB (A + Bh + Bl, 3 stages)
    cudaFuncSetAttribute(gemm_f16<1, true>,
                         cudaFuncAttributeMaxDynamicSharedMemorySize, SM_QKV);
    cudaFuncSetAttribute(gemm_f16<2, false>,
                         cudaFuncAttributeMaxDynamicSharedMemorySize, SM_O);
    cudaFuncSetAttribute(attn_mma,
                         cudaFuncAttributeMaxDynamicSharedMemorySize, ASM_TOTAL);

    convert_x<<<Mn * Cn / 1024, 256>>>(x, xh, Mn * Cn);
    dim3 wgrid(WN / 1024, 4);
    convert_w4<<<wgrid, 256>>>(q_w, k_w, v_w, o_w, wh, wl);

    dim3 qkv_grid(Cn / 128, Mn / 128, 3);
    gemm_f16<1, true><<<qkv_grid, 256, SM_QKV>>>(
        xh, wh, wh, q_b, k_b, v_b, pqh, pkh, pvh, nullptr);

    dim3 attn_grid(Tn / 64, Bn * 16);
    attn_mma<<<attn_grid, 256, ASM_TOTAL>>>(pqh, pkh, pvh, pao);

    dim3 o_grid(Cn / 128, Mn / 128, 1);
    gemm_f16<2, false><<<o_grid, 256, SM_O>>>(
        pao, wh + 3 * (size_t)WN, wl, o_b, o_b, o_b,
        nullptr, nullptr, nullptr, out);
}

// round 6
// speedup vs baseline: 5.6981x; 1.0567x over previous
#include <cuda_runtime.h>
#include <cuda_fp16.h>
#include <cmath>
#include <cstdint>

// Problem constants
constexpr int Bn = 2;
constexpr int Tn = 2048;
constexpr int Cn = 1024;
constexpr int Mn = Bn * Tn;   // 4096
constexpr int WN = Cn * Cn;

// ---------------------------------------------------------------------------
// Scratch (device globals -- no allocation allowed)
// ---------------------------------------------------------------------------
__device__ __align__(256) half g_xh[Mn * Cn];
__device__ __align__(256) half g_wh[4 * WN];     // q,k,v,o weights fp16-hi
__device__ __align__(256) half g_wl[WN];         // o weight fp16-lo only
__device__ __align__(256) half g_qh[Mn * Cn];
__device__ __align__(256) half g_kh[Mn * Cn];
__device__ __align__(256) half g_vh[Mn * Cn];
__device__ __align__(256) half g_ao[Mn * Cn];

// ---------------------------------------------------------------------------
// PTX helpers (base ISA: cp.async / ldmatrix / mma.sync)
// ---------------------------------------------------------------------------
__device__ __forceinline__ uint32_t smem_u32(const void* p) {
    uint32_t a;
    asm("{ .reg .u64 t; cvta.to.shared.u64 t, %1; cvt.u32.u64 %0, t; }"
        : "=r"(a) : "l"(p));
    return a;
}
__device__ __forceinline__ void cp16(uint32_t s, const void* g) {
    asm volatile("cp.async.cg.shared.global [%0], [%1], 16;" :: "r"(s), "l"(g));
}
__device__ __forceinline__ void ldm_x4(uint32_t& r0, uint32_t& r1,
                                       uint32_t& r2, uint32_t& r3, uint32_t a) {
    asm volatile("ldmatrix.sync.aligned.m8n8.x4.shared.b16 {%0,%1,%2,%3}, [%4];"
                 : "=r"(r0), "=r"(r1), "=r"(r2), "=r"(r3) : "r"(a));
}
__device__ __forceinline__ void ldm_x4_t(uint32_t& r0, uint32_t& r1,
                                         uint32_t& r2, uint32_t& r3, uint32_t a) {
    asm volatile("ldmatrix.sync.aligned.m8n8.x4.trans.shared.b16 {%0,%1,%2,%3}, [%4];"
                 : "=r"(r0), "=r"(r1), "=r"(r2), "=r"(r3) : "r"(a));
}
__device__ __forceinline__ void mma_f16(float* c, const uint32_t* a,
                                        const uint32_t* b) {
    asm volatile(
        "mma.sync.aligned.m16n8k16.row.col.f32.f16.f16.f32 "
        "{%0,%1,%2,%3}, {%4,%5,%6,%7}, {%8,%9}, {%0,%1,%2,%3};"
        : "+f"(c[0]), "+f"(c[1]), "+f"(c[2]), "+f"(c[3])
        : "r"(a[0]), "r"(a[1]), "r"(a[2]), "r"(a[3]), "r"(b[0]), "r"(b[1]));
}
__device__ __forceinline__ uint32_t packh2(float x, float y) {
    half2 h = __floats2half2_rn(x, y);
    return *reinterpret_cast<uint32_t*>(&h);
}

// ---------------------------------------------------------------------------
// fp16 GEMM:  out[m][n] = sum_k A[m][k]*W[n][k] + bias[n]
// PASSES=1: W ~ wh only.  PASSES=2: W ~ wh + wl (hi/lo split).
// 128x128 tile, BK=32, 256 threads (8 warps 2x4), warp tile 64x32.
// 4-stage cp.async ring, ONE __syncthreads per K-iter:
//   wait_group(2) -> barrier -> issue(it+3) -> compute(it)
// The barrier at iter it+1 proves all threads finished compute(it) before the
// ring writes stage (it+4) == it (mod 4); wait+barrier publishes stage it.
// ---------------------------------------------------------------------------
constexpr int GBK = 32;
constexpr int KITERS = Cn / GBK;            // 32
constexpr int TIL = 128 * GBK * 2;          // 8192 bytes
constexpr int STAGES = 4;

template <int PASSES, bool F16OUT>
__global__ void __launch_bounds__(256) gemm_f16(
    const half* __restrict__ a,
    const half* __restrict__ wh, const half* __restrict__ wl,
    const float* __restrict__ b0, const float* __restrict__ b1, const float* __restrict__ b2,
    half* oh0, half* oh1, half* oh2, float* of)
{
    constexpr int STG = (1 + PASSES) * TIL;
    extern __shared__ char smem[];
    const uint32_t sb = smem_u32(smem);
    const int tid = threadIdx.x;
    const int z = blockIdx.z;
    const int m0 = blockIdx.y * 128;
    const int n0 = blockIdx.x * 128;

    const half* Bh = wh + (size_t)z * WN;
    const half* Bl = wl;
    const float* bias = (z == 0) ? b0 : (z == 1) ? b1 : b2;
    half* oh = (z == 0) ? oh0 : (z == 1) ? oh1 : oh2;

    const int lane = tid & 31;
    const int wid = tid >> 5;
    const int wm = wid >> 2;
    const int wn = wid & 3;

    const int lrow0 = tid >> 2;
    const int lrow1 = lrow0 + 64;
    const int lc = tid & 3;
    const uint32_t soff0 = (uint32_t)(lrow0 * 64 + ((lc ^ ((lrow0 >> 1) & 3)) << 4));
    const uint32_t soff1 = (uint32_t)(lrow1 * 64 + ((lc ^ ((lrow1 >> 1) & 3)) << 4));

    auto load_stage = [&](int it, int s) {
        const int k0 = it * GBK;
        const uint32_t st = sb + s * STG;
        size_t ga0 = (size_t)(m0 + lrow0) * Cn + k0 + lc * 8;
        size_t ga1 = (size_t)(m0 + lrow1) * Cn + k0 + lc * 8;
        size_t gb0 = (size_t)(n0 + lrow0) * Cn + k0 + lc * 8;
        size_t gb1 = (size_t)(n0 + lrow1) * Cn + k0 + lc * 8;
        cp16(st + soff0,       a + ga0);
        cp16(st + soff1,       a + ga1);
        cp16(st + TIL + soff0, Bh + gb0);
        cp16(st + TIL + soff1, Bh + gb1);
        if (PASSES == 2) {
            cp16(st + 2 * TIL + soff0, Bl + gb0);
            cp16(st + 2 * TIL + soff1, Bl + gb1);
        }
        asm volatile("cp.async.commit_group;" ::: "memory");
    };

    const int arow = wm * 64 + (lane & 15);
    const int brow = wn * 32 + (lane & 7) + ((lane >> 4) << 3);

    float acc[4][4][4];
#pragma unroll
    for (int i = 0; i < 4; i++)
#pragma unroll
        for (int j = 0; j < 4; j++)
#pragma unroll
            for (int r = 0; r < 4; r++) acc[i][j][r] = 0.0f;

    load_stage(0, 0);
    load_stage(1, 1);
    load_stage(2, 2);

    for (int it = 0; it < KITERS; it++) {
        asm volatile("cp.async.wait_group 2;" ::: "memory");
        __syncthreads();
        if (it + (STAGES - 1) < KITERS)
            load_stage(it + (STAGES - 1), (it + (STAGES - 1)) & 3);

        const uint32_t st = sb + (it & 3) * STG;
#pragma unroll
        for (int ks = 0; ks < 2; ks++) {
            uint32_t fah[4][4], fbh[4][2], fbl[4][2];
            const int akc = ks * 2 + (lane >> 4);
#pragma unroll
            for (int mi = 0; mi < 4; mi++) {
                int row = arow + mi * 16;
                uint32_t off = (uint32_t)(row * 64 + ((akc ^ ((row >> 1) & 3)) << 4));
                ldm_x4(fah[mi][0], fah[mi][1], fah[mi][2], fah[mi][3], st + off);
            }
            const int bkc = ks * 2 + ((lane >> 3) & 1);
#pragma unroll
            for (int p = 0; p < 2; p++) {
                int row = brow + p * 16;
                uint32_t off = (uint32_t)(row * 64 + ((bkc ^ ((row >> 1) & 3)) << 4));
                ldm_x4(fbh[2 * p][0], fbh[2 * p][1], fbh[2 * p + 1][0], fbh[2 * p + 1][1],
                       st + TIL + off);
                if (PASSES == 2)
                    ldm_x4(fbl[2 * p][0], fbl[2 * p][1], fbl[2 * p + 1][0], fbl[2 * p + 1][1],
                           st + 2 * TIL + off);
            }
#pragma unroll
            for (int mi = 0; mi < 4; mi++)
#pragma unroll
                for (int ni = 0; ni < 4; ni++) {
                    mma_f16(acc[mi][ni], fah[mi], fbh[ni]);
                    if (PASSES == 2) mma_f16(acc[mi][ni], fah[mi], fbl[ni]);
                }
        }
    }

    // epilogue
#pragma unroll
    for (int mi = 0; mi < 4; mi++) {
#pragma unroll
        for (int hh = 0; hh < 2; hh++) {
            int row = m0 + wm * 64 + mi * 16 + (lane >> 2) + hh * 8;
#pragma unroll
            for (int ni = 0; ni < 4; ni++) {
                int col = n0 + wn * 32 + ni * 8 + (lane & 3) * 2;
                float vx = acc[mi][ni][hh * 2 + 0] + bias[col];
                float vy = acc[mi][ni][hh * 2 + 1] + bias[col + 1];
                if (F16OUT) {
                    *(half2*)&oh[(size_t)row * Cn + col] = __floats2half2_rn(vx, vy);
                } else {
                    float2 o; o.x = vx; o.y = vy;
                    *(float2*)&of[(size_t)row * Cn + col] = o;
                }
            }
        }
    }
}

// ---------------------------------------------------------------------------
// Merged converter: z 0..3 -> weight slices (wh always, wl only z==3),
//                   z 4..7 -> x quarters (fp16 hi only).
// ---------------------------------------------------------------------------
__global__ void __launch_bounds__(256) convert_all(
    const float* __restrict__ x,
    const float* __restrict__ w0, const float* __restrict__ w1,
    const float* __restrict__ w2, const float* __restrict__ w3,
    half* __restrict__ xh, half* __restrict__ wh, half* __restrict__ wl)
{
    const int z = blockIdx.y;
    int i = (blockIdx.x * 256 + threadIdx.x) * 4;
    if (z >= 4) {
        size_t off = (size_t)(z - 4) * WN + i;
        float4 v = *(const float4*)&x[off];
        *(half2*)&xh[off]     = __floats2half2_rn(v.x, v.y);
        *(half2*)&xh[off + 2] = __floats2half2_rn(v.z, v.w);
        return;
    }
    const float* w = (z == 0) ? w0 : (z == 1) ? w1 : (z == 2) ? w2 : w3;
    size_t base = (size_t)z * WN;
    float4 v = *(const float4*)&w[i];
    half2 h0 = __floats2half2_rn(v.x, v.y);
    half2 h1 = __floats2half2_rn(v.z, v.w);
    *(half2*)&wh[base + i]     = h0;
    *(half2*)&wh[base + i + 2] = h1;
    if (z == 3) {
        *(half2*)&wl[i] =
            __floats2half2_rn(v.x - __half2float(h0.x), v.y - __half2float(h0.y));
        *(half2*)&wl[i + 2] =
            __floats2half2_rn(v.z - __half2float(h1.x), v.w - __half2float(h1.y));
    }
}

// ---------------------------------------------------------------------------
// MMA band attention. Block = 64 queries of one (b,h); keys [q0-32, q0+96).
// q,k,v are fp16 values (exact): S = Q K^T single-pass is exact in fp32 acc.
// fp32 softmax; O = P V with P split hi/lo (2-pass).
// 8 warps: 4 m-tiles (16 rows) x 2 key-halves (64 keys). Dead frags skipped.
// ---------------------------------------------------------------------------
constexpr int ASM_QH = 0;          // 8 KB
constexpr int ASM_KH = 8192;       // 16 KB
constexpr int ASM_VH = 24576;      // 16 KB
constexpr int ASM_TOTAL = 40960;

__device__ __forceinline__ uint32_t swz(int row, int chunk) {
    return (uint32_t)(row * 128 + ((chunk ^ (row & 7)) << 4));
}

__global__ void __launch_bounds__(256) attn_mma(
    const half* __restrict__ qh, const half* __restrict__ kh,
    const half* __restrict__ vh, half* __restrict__ ao)
{
    extern __shared__ char smem[];
    const uint32_t sb = smem_u32(smem);
    __shared__ float redmax[2][64];
    __shared__ float redsum[2][64];

    const int tid = threadIdx.x;
    const int lane = tid & 31;
    const int wid = tid >> 5;
    const int wm = wid >> 1;
    const int wn2 = wid & 1;
    const int bh = blockIdx.y;
    const int b = bh >> 4;
    const int h = bh & 15;
    const int q0 = blockIdx.x * 64;

    for (int id = tid; id < 64 * 8; id += 256) {
        int r = id >> 3, c = id & 7;
        size_t g = ((size_t)(b * Tn + q0 + r)) * Cn + h * 64 + c * 8;
        cp16(sb + ASM_QH + swz(r, c), qh + g);
    }
    for (int id = tid; id < 128 * 8; id += 256) {
        int r = id >> 3, c = id & 7;
        int tok = q0 - 32 + r;
        tok = tok < 0 ? 0 : (tok >= Tn ? Tn - 1 : tok);
        uint32_t so = swz(r, c);
        size_t g = ((size_t)(b * Tn + tok)) * Cn + h * 64 + c * 8;
        cp16(sb + ASM_KH + so, kh + g);
        cp16(sb + ASM_VH + so, vh + g);
    }
    asm volatile("cp.async.commit_group;" ::: "memory");
    asm volatile("cp.async.wait_group 0;" ::: "memory");
    __syncthreads();

    const int bandlo = wm * 16;
    const int bandhi = wm * 16 + 80;
    auto live = [&](int nt) {
        int c0 = wn2 * 64 + nt * 8;
        return (c0 + 8 > bandlo) && (c0 < bandhi);
    };

    float sacc[8][4];
#pragma unroll
    for (int i = 0; i < 8; i++)
#pragma unroll
        for (int j = 0; j < 4; j++) sacc[i][j] = 0.0f;

    const int aQrow = wm * 16 + (lane & 15);
    const int aQc = lane >> 4;
    const int bKrow = wn2 * 64 + (lane & 7) + ((lane >> 4) << 3);
    const int bKc = (lane >> 3) & 1;

#pragma unroll
    for (int kc = 0; kc < 4; kc++) {
        uint32_t fah[4];
        ldm_x4(fah[0], fah[1], fah[2], fah[3],
               sb + ASM_QH + swz(aQrow, kc * 2 + aQc));
        uint32_t fbh[8][2];
#pragma unroll
        for (int p = 0; p < 4; p++) {
            if (live(2 * p) || live(2 * p + 1)) {
                uint32_t off = swz(bKrow + p * 16, kc * 2 + bKc);
                ldm_x4(fbh[2 * p][0], fbh[2 * p][1], fbh[2 * p + 1][0], fbh[2 * p + 1][1],
                       sb + ASM_KH + off);
            }
        }
#pragma unroll
        for (int nt = 0; nt < 8; nt++)
            if (live(nt)) mma_f16(sacc[nt], fah, fbh[nt]);
    }

    const int r0 = lane >> 2;
    const int qg0 = q0 + wm * 16 + r0;
    const int qg1 = qg0 + 8;
    float mx[2] = {-1e30f, -1e30f};
#pragma unroll
    for (int nt = 0; nt < 8; nt++) {
        if (live(nt)) {
            int cb = wn2 * 64 + nt * 8 + (lane & 3) * 2;
#pragma unroll
            for (int i = 0; i < 4; i++) {
                int qq = (i < 2) ? qg0 : qg1;
                int jj = q0 - 32 + cb + (i & 1);
                bool ok = (jj >= qq - 32) && (jj < qq + 32) && (jj >= 0) && (jj < Tn);
                float s = ok ? sacc[nt][i] * 0.125f : -1e30f;
                sacc[nt][i] = s;
                mx[i >> 1] = fmaxf(mx[i >> 1], s);
            }
        } else {
#pragma unroll
            for (int i = 0; i < 4; i++) sacc[nt][i] = -1e30f;
        }
    }
#pragma unroll
    for (int j = 0; j < 2; j++) {
        mx[j] = fmaxf(mx[j], __shfl_xor_sync(0xffffffffu, mx[j], 1));
        mx[j] = fmaxf(mx[j], __shfl_xor_sync(0xffffffffu, mx[j], 2));
    }
    if ((lane & 3) == 0) {
        redmax[wn2][wm * 16 + r0] = mx[0];
        redmax[wn2][wm * 16 + r0 + 8] = mx[1];
    }
    __syncthreads();
    float M0 = fmaxf(redmax[0][wm * 16 + r0], redmax[1][wm * 16 + r0]);
    float M1 = fmaxf(redmax[0][wm * 16 + r0 + 8], redmax[1][wm * 16 + r0 + 8]);

    float sm[2] = {0.0f, 0.0f};
#pragma unroll
    for (int nt = 0; nt < 8; nt++) {
        if (live(nt)) {
#pragma unroll
            for (int i = 0; i < 4; i++) {
                float p = __expf(sacc[nt][i] - ((i < 2) ? M0 : M1));
                sacc[nt][i] = p;
                sm[i >> 1] += p;
            }
        } else {
#pragma unroll
            for (int i = 0; i < 4; i++) sacc[nt][i] = 0.0f;
        }
    }
#pragma unroll
    for (int j = 0; j < 2; j++) {
        sm[j] += __shfl_xor_sync(0xffffffffu, sm[j], 1);
        sm[j] += __shfl_xor_sync(0xffffffffu, sm[j], 2);
    }
    if ((lane & 3) == 0) {
        redsum[wn2][wm * 16 + r0] = sm[0];
        redsum[wn2][wm * 16 + r0 + 8] = sm[1];
    }
    __syncthreads();
    const float inv0 = 1.0f / (redsum[0][wm * 16 + r0] + redsum[1][wm * 16 + r0]);
    const float inv1 = 1.0f / (redsum[0][wm * 16 + r0 + 8] + redsum[1][wm * 16 + r0 + 8]);

    float oacc[8][4];
#pragma unroll
    for (int i = 0; i < 8; i++)
#pragma unroll
        for (int j = 0; j < 4; j++) oacc[i][j] = 0.0f;

    const int vrow = wn2 * 64 + ((lane >> 3) & 1) * 8 + (lane & 7);
    const int vc = lane >> 4;

#pragma unroll
    for (int kc = 0; kc < 4; kc++) {
        const int nt0 = 2 * kc, nt1 = 2 * kc + 1;
        if (!(live(nt0) || live(nt1))) continue;
        uint32_t pah[4], pal[4];
        float ps[8] = {sacc[nt0][0], sacc[nt0][1], sacc[nt0][2], sacc[nt0][3],
                       sacc[nt1][0], sacc[nt1][1], sacc[nt1][2], sacc[nt1][3]};
        float pl[8];
#pragma unroll
        for (int i = 0; i < 8; i++) {
            half hv = __float2half_rn(ps[i]);
            pl[i] = ps[i] - __half2float(hv);
        }
        pah[0] = packh2(ps[0], ps[1]); pah[1] = packh2(ps[2], ps[3]);
        pah[2] = packh2(ps[4], ps[5]); pah[3] = packh2(ps[6], ps[7]);
        pal[0] = packh2(pl[0], pl[1]); pal[1] = packh2(pl[2], pl[3]);
        pal[2] = packh2(pl[4], pl[5]); pal[3] = packh2(pl[6], pl[7]);
        uint32_t fvh[8][2];
#pragma unroll
        for (int p = 0; p < 4; p++) {
            uint32_t off = swz(vrow + kc * 16, p * 2 + vc);
            ldm_x4_t(fvh[2 * p][0], fvh[2 * p][1], fvh[2 * p + 1][0], fvh[2 * p + 1][1],
                     sb + ASM_VH + off);
        }
#pragma unroll
        for (int nd = 0; nd < 8; nd++) {
            mma_f16(oacc[nd], pah, fvh[nd]);
            mma_f16(oacc[nd], pal, fvh[nd]);
        }
    }

    float* Obuf = (float*)smem;   // overlays Q + half of K (dead)
    if (wn2 == 0) {
#pragma unroll
        for (int nd = 0; nd < 8; nd++)
#pragma unroll
            for (int i = 0; i < 4; i++) {
                int r = ((i < 2) ? r0 : r0 + 8);
                int d = nd * 8 + (lane & 3) * 2 + (i & 1);
                Obuf[wm * 1024 + r * 64 + d] = oacc[nd][i];
            }
    }
    __syncthreads();
    if (wn2 == 1) {
#pragma unroll
        for (int nd = 0; nd < 8; nd++) {
            int d0 = nd * 8 + (lane & 3) * 2;
            float o00 = (oacc[nd][0] + Obuf[wm * 1024 + r0 * 64 + d0]) * inv0;
            float o01 = (oacc[nd][1] + Obuf[wm * 1024 + r0 * 64 + d0 + 1]) * inv0;
            float o10 = (oacc[nd][2] + Obuf[wm * 1024 + (r0 + 8) * 64 + d0]) * inv1;
            float o11 = (oacc[nd][3] + Obuf[wm * 1024 + (r0 + 8) * 64 + d0 + 1]) * inv1;
            size_t g0 = ((size_t)(b * Tn + qg0)) * Cn + h * 64 + d0;
            size_t g1 = ((size_t)(b * Tn + qg1)) * Cn + h * 64 + d0;
            *(half2*)&ao[g0] = __floats2half2_rn(o00, o01);
            *(half2*)&ao[g1] = __floats2half2_rn(o10, o11);
        }
    }
}

// ---------------------------------------------------------------------------
extern "C" void kernel_launch(void* const* d_in, const int* in_sizes, int n_in,
                              void* d_out, int out_size)
{
    const float* x   = (const float*)d_in[0];
    const float* q_w = (const float*)d_in[1];
    const float* q_b = (const float*)d_in[2];
    const float* k_w = (const float*)d_in[3];
    const float* k_b = (const float*)d_in[4];
    const float* v_w = (const float*)d_in[5];
    const float* v_b = (const float*)d_in[6];
    const float* o_w = (const float*)d_in[7];
    const float* o_b = (const float*)d_in[8];
    float* out = (float*)d_out;

    half *xh, *wh, *wl, *pqh, *pkh, *pvh, *pao;
    cudaGetSymbolAddress((void**)&xh, g_xh);
    cudaGetSymbolAddress((void**)&wh, g_wh);
    cudaGetSymbolAddress((void**)&wl, g_wl);
    cudaGetSymbolAddress((void**)&pqh, g_qh);
    cudaGetSymbolAddress((void**)&pkh, g_kh);
    cudaGetSymbolAddress((void**)&pvh, g_vh);
    cudaGetSymbolAddress((void**)&pao, g_ao);

    constexpr int SM_QKV = STAGES * 2 * TIL;   // 64 KB
    constexpr int SM_O   = STAGES * 3 * TIL;   // 96 KB
    cudaFuncSetAttribute(gemm_f16<1, true>,
                         cudaFuncAttributeMaxDynamicSharedMemorySize, SM_QKV);
    cudaFuncSetAttribute(gemm_f16<2, false>,
                         cudaFuncAttributeMaxDynamicSharedMemorySize, SM_O);
    cudaFuncSetAttribute(attn_mma,
                         cudaFuncAttributeMaxDynamicSharedMemorySize, ASM_TOTAL);

    dim3 cgrid(WN / 1024, 8);   // z 0..3 weights, 4..7 x quarters
    convert_all<<<cgrid, 256>>>(x, q_w, k_w, v_w, o_w, xh, wh, wl);

    dim3 qkv_grid(Cn / 128, Mn / 128, 3);
    gemm_f16<1, true><<<qkv_grid, 256, SM_QKV>>>(
        xh, wh, wh, q_b, k_b, v_b, pqh, pkh, pvh, nullptr);

    dim3 attn_grid(Tn / 64, Bn * 16);
    attn_mma<<<attn_grid, 256, ASM_TOTAL>>>(pqh, pkh, pvh, pao);

    dim3 o_grid(Cn / 128, Mn / 128, 1);
    gemm_f16<2, false><<<o_grid, 256, SM_O>>>(
        pao, wh + 3 * (size_t)WN, wl, o_b, o_b, o_b,
        nullptr, nullptr, nullptr, out);
}